// round 14
// baseline (speedup 1.0000x reference)
#include <cuda_runtime.h>
#include <cuda_fp16.h>
#include <cooperative_groups.h>
#include <cstdint>
#include <cstddef>

namespace cg = cooperative_groups;

// Problem constants
#define EE   384
#define HH   6
#define HSS  64
#define BB   64
#define TT   256
#define FFD  1536
#define NROWS (BB*TT)          // 16384

// ---------------- scratch (device globals; no allocation allowed) ----------
__device__ __half g_qkv_h[(size_t)NROWS * 3 * EE];
__device__ __half g_kv_h[(size_t)NROWS * 2 * EE];
__device__ __half g_q_h[(size_t)NROWS * EE];
__device__ __half g_att_h[(size_t)NROWS * EE];
__device__ __half g_hid_h[(size_t)NROWS * FFD];
__device__ __half g_xh[(size_t)NROWS * EE];
__device__ __half g_ench[(size_t)NROWS * EE];
__device__ __half g_po1h[(size_t)NROWS * EE];
__device__ __half g_po2h[(size_t)NROWS * EE];
// fp16 weights, transposed to [out][in]
__device__ __half g_wqkvh[3 * EE * EE];
__device__ __half g_wq2h[EE * EE];
__device__ __half g_wkvh[2 * EE * EE];
__device__ __half g_wp1h[EE * EE];
__device__ __half g_wp2h[EE * EE];
__device__ __half g_wf1h[FFD * EE];
__device__ __half g_wf2h[EE * FFD];
__device__ float  g_bqkv[3 * EE];
__device__ float  g_bkv[2 * EE];
__device__ float  g_bq2[EE];

// ---------------- PTX helpers ----------------------------------------------
__device__ __forceinline__ uint32_t smem_u32(const void* p) {
    uint32_t a;
    asm("{ .reg .u64 t; cvta.to.shared.u64 t, %1; cvt.u32.u64 %0, t; }" : "=r"(a) : "l"(p));
    return a;
}
__device__ __forceinline__ void cp16(uint32_t dst, const void* src) {
    asm volatile("cp.async.cg.shared.global [%0], [%1], 16;" :: "r"(dst), "l"(src));
}
__device__ __forceinline__ void ldsm4(uint32_t& r0, uint32_t& r1, uint32_t& r2, uint32_t& r3,
                                      uint32_t addr) {
    asm volatile("ldmatrix.sync.aligned.m8n8.x4.shared.b16 {%0,%1,%2,%3}, [%4];"
                 : "=r"(r0), "=r"(r1), "=r"(r2), "=r"(r3) : "r"(addr));
}
__device__ __forceinline__ void ldsm4t(uint32_t& r0, uint32_t& r1, uint32_t& r2, uint32_t& r3,
                                       uint32_t addr) {
    asm volatile("ldmatrix.sync.aligned.m8n8.x4.trans.shared.b16 {%0,%1,%2,%3}, [%4];"
                 : "=r"(r0), "=r"(r1), "=r"(r2), "=r"(r3) : "r"(addr));
}
__device__ __forceinline__ void mma16816(float* c, const uint32_t* a, const uint32_t* b) {
    asm volatile(
        "mma.sync.aligned.m16n8k16.row.col.f32.f16.f16.f32 "
        "{%0,%1,%2,%3}, {%4,%5,%6,%7}, {%8,%9}, {%0,%1,%2,%3};"
        : "+f"(c[0]), "+f"(c[1]), "+f"(c[2]), "+f"(c[3])
        : "r"(a[0]), "r"(a[1]), "r"(a[2]), "r"(a[3]), "r"(b[0]), "r"(b[1]));
}
__device__ __forceinline__ uint32_t ph2(float a, float b) {
    __half2 h = __floats2half2_rn(a, b);
    return *reinterpret_cast<uint32_t*>(&h);
}
__device__ __forceinline__ uint32_t sw_off(int r, int seg) {
    return (uint32_t)(r * 128 + (((seg ^ (r & 7)) & 7) << 4));
}

// ---------------- shared 32x32 transpose tile -------------------------------
__device__ __forceinline__ void transpose32(const float* __restrict__ src, int lds,
                                            __half* __restrict__ dst, int ldd,
                                            int r0, int c0, float scale, int tid) {
    __shared__ float ttile[32][33];
    int tx = tid & 31, ty = tid >> 5;
#pragma unroll
    for (int i = 0; i < 4; i++) {
        int row = ty + i * 8;
        ttile[row][tx] = src[(size_t)(r0 + row) * lds + c0 + tx] * scale;
    }
    __syncthreads();
#pragma unroll
    for (int i = 0; i < 4; i++) {
        int row = ty + i * 8;
        dst[(size_t)(c0 + row) * ldd + r0 + tx] = __float2half_rn(ttile[tx][row]);
    }
}

// ---------------- packA: critical path -------------------------------------
#define PA_T   720
#define PA_B   (PA_T + 9)
#define NACTV  ((long long)((size_t)NROWS * EE / 4))
#define PA_TOTAL (PA_B + 12288)

__global__ void __launch_bounds__(256)
packA_kernel(
    const float* __restrict__ wq1, const float* __restrict__ wk1, const float* __restrict__ wv1,
    const float* __restrict__ wk2, const float* __restrict__ wv2,
    const float* __restrict__ bq1, const float* __restrict__ bk1, const float* __restrict__ bv1,
    const float* __restrict__ bq2, const float* __restrict__ bk2, const float* __restrict__ bv2,
    const float* __restrict__ x, const float* __restrict__ enc,
    __half* __restrict__ wqkv, __half* __restrict__ wkv,
    float* __restrict__ bqkv, float* __restrict__ bkv, float* __restrict__ bq2o,
    __half* __restrict__ xh, __half* __restrict__ ench)
{
    int bid = blockIdx.x, tid = threadIdx.x;
    if (bid < PA_T) {
        int tensor = bid / 144, rem = bid % 144;
        int h = rem / 24, t = rem % 24;
        int r0 = (t >> 1) * 32, c0 = (t & 1) * 32;
        const float* srcs[5] = {wq1, wk1, wv1, wk2, wv2};
        const float* src = srcs[tensor] + (size_t)h * EE * HSS;
        __half* dst; int rowoff;
        if (tensor < 3) { dst = wqkv; rowoff = tensor * EE; }
        else            { dst = wkv;  rowoff = (tensor - 3) * EE; }
        dst += (size_t)(rowoff + h * HSS) * EE;
        float scale = (tensor == 0) ? rsqrtf((float)EE) : 1.0f;
        transpose32(src, HSS, dst, EE, r0, c0, scale, tid);
        return;
    }
    if (bid < PA_B) {
        int i = (bid - PA_T) * 256 + tid;
        float scale = rsqrtf((float)EE);
        if (i < 3 * EE) {
            int sub = i / EE, jj = i % EE;
            bqkv[i] = sub == 0 ? bq1[jj] * scale : sub == 1 ? bk1[jj] : bv1[jj];
        } else if (i < 5 * EE) {
            int k = i - 3 * EE;
            bkv[k] = k < EE ? bk2[k] : bv2[k - EE];
        } else {
            int k = i - 5 * EE;
            bq2o[k] = bq2[k] * scale;
        }
        return;
    }
    long long ai = (long long)(bid - PA_B) * 256 + tid;
    const float* srcf; __half* dsth;
    if (ai < NACTV) { srcf = x; dsth = xh; }
    else { ai -= NACTV; srcf = enc; dsth = ench; }
    float4 v4 = ((const float4*)srcf)[ai];
    ((__half2*)dsth)[2 * ai]     = __floats2half2_rn(v4.x, v4.y);
    ((__half2*)dsth)[2 * ai + 1] = __floats2half2_rn(v4.z, v4.w);
}

// ---------------- packB: off-critical-path weight transposes ----------------
#define PB_WQ2 144
#define PB_PW  (PB_WQ2 + 288)
#define PB_F1  (PB_PW + 576)
#define PB_TOTAL (PB_F1 + 576)

__global__ void __launch_bounds__(256)
packB_kernel(const float* __restrict__ wq2,
             const float* __restrict__ pw1, const float* __restrict__ pw2,
             const float* __restrict__ fw1, const float* __restrict__ fw2,
             __half* __restrict__ wqo, __half* __restrict__ wp1o, __half* __restrict__ wp2o,
             __half* __restrict__ wf1o, __half* __restrict__ wf2o)
{
    int bid = blockIdx.x, tid = threadIdx.x;
    if (bid < PB_WQ2) {
        int h = bid / 24, t = bid % 24;
        int r0 = (t >> 1) * 32, c0 = (t & 1) * 32;
        transpose32(wq2 + (size_t)h * EE * HSS, HSS,
                    wqo + (size_t)(h * HSS) * EE, EE,
                    r0, c0, rsqrtf((float)EE), tid);
    } else if (bid < PB_PW) {
        int j = bid - PB_WQ2, which = j / 144, t = j % 144;
        int r0 = (t / 12) * 32, c0 = (t % 12) * 32;
        transpose32(which ? pw2 : pw1, EE, which ? wp2o : wp1o, EE, r0, c0, 1.0f, tid);
    } else if (bid < PB_F1) {
        int t = bid - PB_PW;
        int r0 = (t / 48) * 32, c0 = (t % 48) * 32;
        transpose32(fw1, FFD, wf1o, EE, r0, c0, 1.0f, tid);
    } else {
        int t = bid - PB_F1;
        int r0 = (t / 12) * 32, c0 = (t % 12) * 32;
        transpose32(fw2, EE, wf2o, FFD, r0, c0, 1.0f, tid);
    }
}

// ---------------- fp16 tensor-core GEMM mainloop (128x128, BK=64) -----------
#define G16_SMEM (3 * 32768)

template <int K>
__device__ __forceinline__ void load_chunk(uint32_t sbase,
                                           const __half* __restrict__ A,
                                           const __half* __restrict__ Wt,
                                           int row0, int col0, int tid,
                                           int stage, int kt) {
    uint32_t sA = sbase + (uint32_t)stage * 32768u;
    uint32_t sB = sA + 16384u;
#pragma unroll
    for (int i = 0; i < 4; i++) {
        int li = tid + i * 256; int r = li >> 3, sg = li & 7;
        cp16(sA + sw_off(r, sg), A + (size_t)(row0 + r) * K + kt + sg * 8);
        cp16(sB + sw_off(r, sg), Wt + (size_t)(col0 + r) * K + kt + sg * 8);
    }
    asm volatile("cp.async.commit_group;");
}

template <int K>
__device__ __forceinline__ void gemm_mainloop(float acc[4][4][4],
                                              const __half* __restrict__ A,
                                              const __half* __restrict__ Wt,
                                              int row0, int col0, int tid,
                                              int wm, int wn, int j, int rr,
                                              uint32_t sbase)
{
    constexpr int nch = K >> 6;
    load_chunk<K>(sbase, A, Wt, row0, col0, tid, 0, 0);
    load_chunk<K>(sbase, A, Wt, row0, col0, tid, 1, 64);
#pragma unroll 2
    for (int it = 0; it < nch; it++) {
        if (it + 1 < nch) asm volatile("cp.async.wait_group 1;");
        else              asm volatile("cp.async.wait_group 0;");
        __syncthreads();
        if (it + 2 < nch)
            load_chunk<K>(sbase, A, Wt, row0, col0, tid, (it + 2) % 3, (it + 2) * 64);
        uint32_t sA = sbase + (uint32_t)(it % 3) * 32768u;
        uint32_t sB = sA + 16384u;
#pragma unroll
        for (int ks = 0; ks < 4; ks++) {
            uint32_t a[4][4], bfr[2][4];
#pragma unroll
            for (int mt = 0; mt < 4; mt++)
                ldsm4(a[mt][0], a[mt][1], a[mt][2], a[mt][3],
                      sA + sw_off(wm * 64 + mt * 16 + (j & 1) * 8 + rr, ks * 2 + (j >> 1)));
#pragma unroll
            for (int p = 0; p < 2; p++)
                ldsm4(bfr[p][0], bfr[p][1], bfr[p][2], bfr[p][3],
                      sB + sw_off(wn * 32 + p * 16 + (j >> 1) * 8 + rr, ks * 2 + (j & 1)));
#pragma unroll
            for (int mt = 0; mt < 4; mt++)
#pragma unroll
                for (int nt = 0; nt < 4; nt++)
                    mma16816(acc[mt][nt], a[mt], &bfr[nt >> 1][(nt & 1) * 2]);
        }
    }
}

// ---------------- plain GEMM (bias, opt resid/relu, fp16 out) ---------------
template <int K>
__global__ void __launch_bounds__(256, 2)
gemm_std(const __half* __restrict__ A, const __half* __restrict__ Wt,
         const float* __restrict__ bias, const __half* __restrict__ resid,
         __half* __restrict__ Ch, int M, int relu)
{
    extern __shared__ char gsm[];
    uint32_t sbase = smem_u32(gsm);
    int tid = threadIdx.x, lane = tid & 31, warp = tid >> 5;
    int wm = warp >> 2, wn = warp & 3;
    int gid = lane >> 2, tg = lane & 3;
    int j = lane >> 3, rr = lane & 7;
    int col0 = blockIdx.x * 128, row0 = blockIdx.y * 128;

    float acc[4][4][4];
#pragma unroll
    for (int a = 0; a < 4; a++)
#pragma unroll
        for (int b = 0; b < 4; b++)
#pragma unroll
            for (int c = 0; c < 4; c++) acc[a][b][c] = 0.0f;

    gemm_mainloop<K>(acc, A, Wt, row0, col0, tid, wm, wn, j, rr, sbase);

#pragma unroll
    for (int mt = 0; mt < 4; mt++)
#pragma unroll
        for (int nt = 0; nt < 4; nt++) {
            int r0 = row0 + wm * 64 + mt * 16 + gid;
            int c0 = col0 + wn * 32 + nt * 8 + tg * 2;
            float b0 = bias[c0], b1 = bias[c0 + 1];
            float v0 = acc[mt][nt][0] + b0, v1 = acc[mt][nt][1] + b1;
            float v2 = acc[mt][nt][2] + b0, v3 = acc[mt][nt][3] + b1;
            if (resid) {
                float2 ra = __half22float2(*(const __half2*)(resid + (size_t)r0 * M + c0));
                float2 rb = __half22float2(*(const __half2*)(resid + (size_t)(r0 + 8) * M + c0));
                v0 += ra.x; v1 += ra.y; v2 += rb.x; v3 += rb.y;
            }
            if (relu) {
                v0 = fmaxf(v0, 0.f); v1 = fmaxf(v1, 0.f);
                v2 = fmaxf(v2, 0.f); v3 = fmaxf(v3, 0.f);
            }
            *(__half2*)(Ch + (size_t)r0 * M + c0)       = __floats2half2_rn(v0, v1);
            *(__half2*)(Ch + (size_t)(r0 + 8) * M + c0) = __floats2half2_rn(v2, v3);
        }
}

// ---------------- fused GEMM + residual + LayerNorm (3-CTA cluster) ---------
// M == 384: 3 column-tile CTAs per row-block form a cluster; full-row LN
// stats via smem atomics + DSMEM combine; writes final LN output directly.
template <int K, bool F32OUT>
__global__ void __launch_bounds__(256, 2) __cluster_dims__(3, 1, 1)
gemm_ln(const __half* __restrict__ A, const __half* __restrict__ Wt,
        const float* __restrict__ bias, const __half* __restrict__ resid,
        const float* __restrict__ lng, const float* __restrict__ lnb,
        __half* __restrict__ Oh, float* __restrict__ Of)
{
    extern __shared__ char gsm[];
    __shared__ float s_sum[128], s_sq[128], s_mean[128], s_inv[128];
    uint32_t sbase = smem_u32(gsm);
    int tid = threadIdx.x, lane = tid & 31, warp = tid >> 5;
    int wm = warp >> 2, wn = warp & 3;
    int gid = lane >> 2, tg = lane & 3;
    int j = lane >> 3, rr = lane & 7;
    int col0 = blockIdx.x * 128, row0 = blockIdx.y * 128;
    const int M = 384;

    if (tid < 128) { s_sum[tid] = 0.0f; s_sq[tid] = 0.0f; }

    float acc[4][4][4];
#pragma unroll
    for (int a = 0; a < 4; a++)
#pragma unroll
        for (int b = 0; b < 4; b++)
#pragma unroll
            for (int c = 0; c < 4; c++) acc[a][b][c] = 0.0f;

    gemm_mainloop<K>(acc, A, Wt, row0, col0, tid, wm, wn, j, rr, sbase);
    // mainloop's final __syncthreads has occurred; s_sum zeroing is visible

    // bias + residual into acc; accumulate per-row partials
#pragma unroll
    for (int mt = 0; mt < 4; mt++) {
        int r0 = row0 + wm * 64 + mt * 16 + gid;
        float ps0 = 0.f, sq0 = 0.f, ps1 = 0.f, sq1 = 0.f;
#pragma unroll
        for (int nt = 0; nt < 4; nt++) {
            int c0 = col0 + wn * 32 + nt * 8 + tg * 2;
            float b0 = bias[c0], b1 = bias[c0 + 1];
            float2 ra = __half22float2(*(const __half2*)(resid + (size_t)r0 * M + c0));
            float2 rb = __half22float2(*(const __half2*)(resid + (size_t)(r0 + 8) * M + c0));
            float v0 = acc[mt][nt][0] + b0 + ra.x;
            float v1 = acc[mt][nt][1] + b1 + ra.y;
            float v2 = acc[mt][nt][2] + b0 + rb.x;
            float v3 = acc[mt][nt][3] + b1 + rb.y;
            acc[mt][nt][0] = v0; acc[mt][nt][1] = v1;
            acc[mt][nt][2] = v2; acc[mt][nt][3] = v3;
            ps0 += v0 + v1; sq0 += v0 * v0 + v1 * v1;
            ps1 += v2 + v3; sq1 += v2 * v2 + v3 * v3;
        }
        // reduce over tg (lanes gid*4 + tg, xor 1/2 flips tg only)
        ps0 += __shfl_xor_sync(~0u, ps0, 1); ps0 += __shfl_xor_sync(~0u, ps0, 2);
        sq0 += __shfl_xor_sync(~0u, sq0, 1); sq0 += __shfl_xor_sync(~0u, sq0, 2);
        ps1 += __shfl_xor_sync(~0u, ps1, 1); ps1 += __shfl_xor_sync(~0u, ps1, 2);
        sq1 += __shfl_xor_sync(~0u, sq1, 1); sq1 += __shfl_xor_sync(~0u, sq1, 2);
        if (tg == 0) {
            int rl = wm * 64 + mt * 16 + gid;
            atomicAdd(&s_sum[rl], ps0); atomicAdd(&s_sq[rl], sq0);
            atomicAdd(&s_sum[rl + 8], ps1); atomicAdd(&s_sq[rl + 8], sq1);
        }
    }

    cg::cluster_group cluster = cg::this_cluster();
    cluster.sync();
    if (tid < 128) {
        float ssum = 0.f, ssq = 0.f;
#pragma unroll
        for (int rk = 0; rk < 3; rk++) {
            const float* psu = cluster.map_shared_rank(s_sum, rk);
            const float* psq = cluster.map_shared_rank(s_sq, rk);
            ssum += psu[tid]; ssq += psq[tid];
        }
        float mean = ssum * (1.0f / EE);
        float var = ssq * (1.0f / EE) - mean * mean;
        s_mean[tid] = mean;
        s_inv[tid] = rsqrtf(var + 1e-5f);
    }
    cluster.sync();

#pragma unroll
    for (int mt = 0; mt < 4; mt++) {
        int rl = wm * 64 + mt * 16 + gid;
        int r0 = row0 + rl;
        float m0 = s_mean[rl],     i0 = s_inv[rl];
        float m1 = s_mean[rl + 8], i1 = s_inv[rl + 8];
#pragma unroll
        for (int nt = 0; nt < 4; nt++) {
            int c0 = col0 + wn * 32 + nt * 8 + tg * 2;
            float g0 = lng[c0], g1 = lng[c0 + 1];
            float bb0 = lnb[c0], bb1 = lnb[c0 + 1];
            float v0 = (acc[mt][nt][0] - m0) * i0 * g0 + bb0;
            float v1 = (acc[mt][nt][1] - m0) * i0 * g1 + bb1;
            float v2 = (acc[mt][nt][2] - m1) * i1 * g0 + bb0;
            float v3 = (acc[mt][nt][3] - m1) * i1 * g1 + bb1;
            if (F32OUT) {
                *(float2*)(Of + (size_t)r0 * M + c0)       = make_float2(v0, v1);
                *(float2*)(Of + (size_t)(r0 + 8) * M + c0) = make_float2(v2, v3);
            } else {
                *(__half2*)(Oh + (size_t)r0 * M + c0)       = __floats2half2_rn(v0, v1);
                *(__half2*)(Oh + (size_t)(r0 + 8) * M + c0) = __floats2half2_rn(v2, v3);
            }
        }
    }
}

// ---------------- flash attention: 128 q-rows per CTA, 8 warps --------------
#define AT_SMEM (16384 + 2 * 16384)

__global__ void __launch_bounds__(256, 2)
attn16_kernel(const __half* __restrict__ Qg, int ldq,
              const __half* __restrict__ Kg, const __half* __restrict__ Vg, int ldkv,
              __half* __restrict__ Og)
{
    extern __shared__ __align__(128) char asmem[];
    uint32_t sbase = smem_u32(asmem);
    uint32_t sQ = sbase;
    int tid = threadIdx.x, lane = tid & 31, w = tid >> 5;
    int gid = lane >> 2, tg = lane & 3;
    int j = lane >> 3, rr = lane & 7;

    int bid = blockIdx.x;
    int qt = (bid & 1) ^ 1;
    int h = (bid >> 1) % HH, b = bid / (2 * HH);
    int t0 = qt * 128;
    int hoff = h * HSS;

    const __half* qrow = Qg + (size_t)(b * TT + t0) * ldq + hoff;
#pragma unroll
    for (int i = 0; i < 4; i++) {
        int li = tid + i * 256; int r = li >> 3, sg = li & 7;
        cp16(sQ + sw_off(r, sg), qrow + (size_t)r * ldq + sg * 8);
    }
#define KVLOAD(ut, bufi)                                                           \
    {                                                                              \
        uint32_t sK_ = sbase + 16384u + (uint32_t)(bufi) * 16384u;                 \
        uint32_t sV_ = sK_ + 8192u;                                                \
        const __half* kr = Kg + (size_t)(b * TT + (ut) * 64) * ldkv + hoff;        \
        const __half* vr = Vg + (size_t)(b * TT + (ut) * 64) * ldkv + hoff;        \
        _Pragma("unroll")                                                          \
        for (int i = 0; i < 2; i++) {                                              \
            int li = tid + i * 256; int r = li >> 3, sg = li & 7;                  \
            cp16(sK_ + sw_off(r, sg), kr + (size_t)r * ldkv + sg * 8);             \
            cp16(sV_ + sw_off(r, sg), vr + (size_t)r * ldkv + sg * 8);             \
        }                                                                          \
        asm volatile("cp.async.commit_group;");                                    \
    }
    KVLOAD(0, 0);
    asm volatile("cp.async.wait_group 0;");
    __syncthreads();

    uint32_t qf[4][4];
#pragma unroll
    for (int ks = 0; ks < 4; ks++)
        ldsm4(qf[ks][0], qf[ks][1], qf[ks][2], qf[ks][3],
              sQ + sw_off(w * 16 + (j & 1) * 8 + rr, ks * 2 + (j >> 1)));

    float o[8][4];
#pragma unroll
    for (int nt = 0; nt < 8; nt++)
#pragma unroll
        for (int e = 0; e < 4; e++) o[nt][e] = 0.0f;
    float m0 = -1e30f, m1 = -1e30f, l0 = 0.0f, l1 = 0.0f;

    int nkv = 2 * (qt + 1);
    int r0g = t0 + w * 16 + gid;
    for (int ut = 0; ut < nkv; ut++) {
        if (ut > 0) { asm volatile("cp.async.wait_group 0;"); __syncthreads(); }
        if (ut < nkv - 1) KVLOAD(ut + 1, (ut + 1) & 1);
        uint32_t sK = sbase + 16384u + (uint32_t)(ut & 1) * 16384u;
        uint32_t sV = sK + 8192u;

        float s[8][4];
#pragma unroll
        for (int nt = 0; nt < 8; nt++)
#pragma unroll
            for (int e = 0; e < 4; e++) s[nt][e] = 0.0f;
#pragma unroll
        for (int ks = 0; ks < 4; ks++) {
            uint32_t kb[4][4];
#pragma unroll
            for (int p = 0; p < 4; p++)
                ldsm4(kb[p][0], kb[p][1], kb[p][2], kb[p][3],
                      sK + sw_off(p * 16 + (j >> 1) * 8 + rr, ks * 2 + (j & 1)));
#pragma unroll
            for (int nt = 0; nt < 8; nt++)
                mma16816(s[nt], qf[ks], &kb[nt >> 1][(nt & 1) * 2]);
        }
        if (ut >= 2 * qt) {
#pragma unroll
            for (int nt = 0; nt < 8; nt++) {
                int u0 = ut * 64 + nt * 8 + tg * 2;
                if (u0     > r0g)     s[nt][0] = -1e30f;
                if (u0 + 1 > r0g)     s[nt][1] = -1e30f;
                if (u0     > r0g + 8) s[nt][2] = -1e30f;
                if (u0 + 1 > r0g + 8) s[nt][3] = -1e30f;
            }
        }
        float mx0 = -1e30f, mx1 = -1e30f;
#pragma unroll
        for (int nt = 0; nt < 8; nt++) {
            mx0 = fmaxf(mx0, fmaxf(s[nt][0], s[nt][1]));
            mx1 = fmaxf(mx1, fmaxf(s[nt][2], s[nt][3]));
        }
        mx0 = fmaxf(mx0, __shfl_xor_sync(~0u, mx0, 1));
        mx0 = fmaxf(mx0, __shfl_xor_sync(~0u, mx0, 2));
        mx1 = fmaxf(mx1, __shfl_xor_sync(~0u, mx1, 1));
        mx1 = fmaxf(mx1, __shfl_xor_sync(~0u, mx1, 2));
        float mn0 = fmaxf(m0, mx0), mn1 = fmaxf(m1, mx1);
        float f0 = __expf(m0 - mn0), f1 = __expf(m1 - mn1);
        m0 = mn0; m1 = mn1;
        float rs0 = 0.0f, rs1 = 0.0f;
#pragma unroll
        for (int nt = 0; nt < 8; nt++) {
            s[nt][0] = __expf(s[nt][0] - mn0); rs0 += s[nt][0];
            s[nt][1] = __expf(s[nt][1] - mn0); rs0 += s[nt][1];
            s[nt][2] = __expf(s[nt][2] - mn1); rs1 += s[nt][2];
            s[nt][3] = __expf(s[nt][3] - mn1); rs1 += s[nt][3];
        }
        rs0 += __shfl_xor_sync(~0u, rs0, 1); rs0 += __shfl_xor_sync(~0u, rs0, 2);
        rs1 += __shfl_xor_sync(~0u, rs1, 1); rs1 += __shfl_xor_sync(~0u, rs1, 2);
        l0 = l0 * f0 + rs0;
        l1 = l1 * f1 + rs1;
#pragma unroll
        for (int nt = 0; nt < 8; nt++) {
            o[nt][0] *= f0; o[nt][1] *= f0; o[nt][2] *= f1; o[nt][3] *= f1;
        }
        uint32_t pa[4][4];
#pragma unroll
        for (int kk = 0; kk < 4; kk++) {
            pa[kk][0] = ph2(s[2 * kk][0], s[2 * kk][1]);
            pa[kk][1] = ph2(s[2 * kk][2], s[2 * kk][3]);
            pa[kk][2] = ph2(s[2 * kk + 1][0], s[2 * kk + 1][1]);
            pa[kk][3] = ph2(s[2 * kk + 1][2], s[2 * kk + 1][3]);
        }
#pragma unroll
        for (int kk = 0; kk < 4; kk++) {
            uint32_t vb[4][4];
#pragma unroll
            for (int p = 0; p < 4; p++)
                ldsm4t(vb[p][0], vb[p][1], vb[p][2], vb[p][3],
                       sV + sw_off(kk * 16 + (j & 1) * 8 + rr, p * 2 + (j >> 1)));
#pragma unroll
            for (int nt = 0; nt < 8; nt++)
                mma16816(o[nt], pa[kk], &vb[nt >> 1][(nt & 1) * 2]);
        }
    }
    float i0 = 1.0f / l0, i1 = 1.0f / l1;
    __half* orow = Og + (size_t)(b * TT + t0) * EE + hoff;
#pragma unroll
    for (int nt = 0; nt < 8; nt++) {
        int c = nt * 8 + tg * 2;
        *(__half2*)(orow + (size_t)(w * 16 + gid) * EE + c) =
            __floats2half2_rn(o[nt][0] * i0, o[nt][1] * i0);
        *(__half2*)(orow + (size_t)(w * 16 + gid + 8) * EE + c) =
            __floats2half2_rn(o[nt][2] * i1, o[nt][3] * i1);
    }
}

// ---------------- host orchestration ---------------------------------------
extern "C" void kernel_launch(void* const* d_in, const int* in_sizes, int n_in,
                              void* d_out, int out_size) {
    const float* enc = (const float*)d_in[0];
    const float* x   = (const float*)d_in[1];
    const float* sa1_wq = (const float*)d_in[2];
    const float* sa1_bq = (const float*)d_in[3];
    const float* sa1_wk = (const float*)d_in[4];
    const float* sa1_bk = (const float*)d_in[5];
    const float* sa1_wv = (const float*)d_in[6];
    const float* sa1_bv = (const float*)d_in[7];
    const float* sa1_pw = (const float*)d_in[8];
    const float* sa1_pb = (const float*)d_in[9];
    const float* sa2_wq = (const float*)d_in[10];
    const float* sa2_bq = (const float*)d_in[11];
    const float* sa2_wk = (const float*)d_in[12];
    const float* sa2_bk = (const float*)d_in[13];
    const float* sa2_wv = (const float*)d_in[14];
    const float* sa2_bv = (const float*)d_in[15];
    const float* sa2_pw = (const float*)d_in[16];
    const float* sa2_pb = (const float*)d_in[17];
    const float* ff_w1  = (const float*)d_in[18];
    const float* ff_b1  = (const float*)d_in[19];
    const float* ff_w2  = (const float*)d_in[20];
    const float* ff_b2  = (const float*)d_in[21];
    const float* ln1_g  = (const float*)d_in[22];
    const float* ln1_b  = (const float*)d_in[23];
    const float* ln2_g  = (const float*)d_in[24];
    const float* ln2_b  = (const float*)d_in[25];
    const float* ln3_g  = (const float*)d_in[26];
    const float* ln3_b  = (const float*)d_in[27];
    float* out = (float*)d_out;

    static cudaStream_t s_aux = nullptr;
    static cudaEvent_t evFork = nullptr, evActs = nullptr, evW = nullptr, evKV = nullptr;
    if (!s_aux) {
        cudaStreamCreateWithFlags(&s_aux, cudaStreamNonBlocking);
        cudaEventCreateWithFlags(&evFork, cudaEventDisableTiming);
        cudaEventCreateWithFlags(&evActs, cudaEventDisableTiming);
        cudaEventCreateWithFlags(&evW,    cudaEventDisableTiming);
        cudaEventCreateWithFlags(&evKV,   cudaEventDisableTiming);
        cudaFuncSetAttribute(gemm_std<384>,
                             cudaFuncAttributeMaxDynamicSharedMemorySize, G16_SMEM);
        cudaFuncSetAttribute(gemm_std<1536>,
                             cudaFuncAttributeMaxDynamicSharedMemorySize, G16_SMEM);
        cudaFuncSetAttribute(gemm_ln<384, false>,
                             cudaFuncAttributeMaxDynamicSharedMemorySize, G16_SMEM);
        cudaFuncSetAttribute(gemm_ln<1536, true>,
                             cudaFuncAttributeMaxDynamicSharedMemorySize, G16_SMEM);
        cudaFuncSetAttribute(attn16_kernel,
                             cudaFuncAttributeMaxDynamicSharedMemorySize, AT_SMEM);
    }

    __half *pqkv, *pkv, *pq, *patt, *phid, *pxh, *pench, *po1h, *po2h;
    __half *pwqkv, *pwq2, *pwkv, *pwp1, *pwp2, *pwf1, *pwf2;
    float *pbqkv, *pbkv, *pbq2;
    cudaGetSymbolAddress((void**)&pqkv,  g_qkv_h);
    cudaGetSymbolAddress((void**)&pkv,   g_kv_h);
    cudaGetSymbolAddress((void**)&pq,    g_q_h);
    cudaGetSymbolAddress((void**)&patt,  g_att_h);
    cudaGetSymbolAddress((void**)&phid,  g_hid_h);
    cudaGetSymbolAddress((void**)&pxh,   g_xh);
    cudaGetSymbolAddress((void**)&pench, g_ench);
    cudaGetSymbolAddress((void**)&po1h,  g_po1h);
    cudaGetSymbolAddress((void**)&po2h,  g_po2h);
    cudaGetSymbolAddress((void**)&pwqkv, g_wqkvh);
    cudaGetSymbolAddress((void**)&pwq2,  g_wq2h);
    cudaGetSymbolAddress((void**)&pwkv,  g_wkvh);
    cudaGetSymbolAddress((void**)&pwp1,  g_wp1h);
    cudaGetSymbolAddress((void**)&pwp2,  g_wp2h);
    cudaGetSymbolAddress((void**)&pwf1,  g_wf1h);
    cudaGetSymbolAddress((void**)&pwf2,  g_wf2h);
    cudaGetSymbolAddress((void**)&pbqkv, g_bqkv);
    cudaGetSymbolAddress((void**)&pbkv,  g_bkv);
    cudaGetSymbolAddress((void**)&pbq2,  g_bq2);

    cudaEventRecord(evFork, 0);
    cudaStreamWaitEvent(s_aux, evFork, 0);

    packB_kernel<<<PB_TOTAL, 256, 0, s_aux>>>(
        sa2_wq, sa1_pw, sa2_pw, ff_w1, ff_w2,
        pwq2, pwp1, pwp2, pwf1, pwf2);
    cudaEventRecord(evW, s_aux);

    packA_kernel<<<PA_TOTAL, 256>>>(
        sa1_wq, sa1_wk, sa1_wv, sa2_wk, sa2_wv,
        sa1_bq, sa1_bk, sa1_bv, sa2_bq, sa2_bk, sa2_bv,
        x, enc,
        pwqkv, pwkv, pbqkv, pbkv, pbq2, pxh, pench);
    cudaEventRecord(evActs, 0);

    cudaStreamWaitEvent(s_aux, evActs, 0);
    gemm_std<384><<<dim3(6, 128), 256, G16_SMEM, s_aux>>>(
        pench, pwkv, pbkv, nullptr, pkv, 2 * EE, 0);
    cudaEventRecord(evKV, s_aux);

    gemm_std<384><<<dim3(9, 128), 256, G16_SMEM>>>(
        pxh, pwqkv, pbqkv, nullptr, pqkv, 3 * EE, 0);
    attn16_kernel<<<BB * HH * 2, 256, AT_SMEM>>>(pqkv, 3 * EE,
                                                 pqkv + EE, pqkv + 2 * EE, 3 * EE, patt);

    cudaStreamWaitEvent(0, evW, 0);
    gemm_ln<384, false><<<dim3(3, 128), 256, G16_SMEM>>>(
        patt, pwp1, sa1_pb, pxh, ln1_g, ln1_b, po1h, nullptr);

    gemm_std<384><<<dim3(3, 128), 256, G16_SMEM>>>(
        po1h, pwq2, pbq2, nullptr, pq, EE, 0);
    cudaStreamWaitEvent(0, evKV, 0);
    attn16_kernel<<<BB * HH * 2, 256, AT_SMEM>>>(pq, EE,
                                                 pkv, pkv + EE, 2 * EE, patt);
    gemm_ln<384, false><<<dim3(3, 128), 256, G16_SMEM>>>(
        patt, pwp2, sa2_pb, po1h, ln2_g, ln2_b, po2h, nullptr);

    gemm_std<384><<<dim3(12, 128), 256, G16_SMEM>>>(
        po2h, pwf1, ff_b1, nullptr, phid, FFD, 1);
    gemm_ln<1536, true><<<dim3(3, 128), 256, G16_SMEM>>>(
        phid, pwf2, ff_b2, po2h, ln3_g, ln3_b, nullptr, out);
}

// round 15
// speedup vs baseline: 1.0118x; 1.0118x over previous
#include <cuda_runtime.h>
#include <cuda_fp16.h>
#include <cooperative_groups.h>
#include <cstdint>
#include <cstddef>

namespace cg = cooperative_groups;

// Problem constants
#define EE   384
#define HH   6
#define HSS  64
#define BB   64
#define TT   256
#define FFD  1536
#define NROWS (BB*TT)          // 16384

// ---------------- scratch (device globals; no allocation allowed) ----------
__device__ __half g_qkv_h[(size_t)NROWS * 3 * EE];
__device__ __half g_kv_h[(size_t)NROWS * 2 * EE];
__device__ __half g_q_h[(size_t)NROWS * EE];
__device__ __half g_att_h[(size_t)NROWS * EE];
__device__ __half g_hid_h[(size_t)NROWS * FFD];
__device__ __half g_xh[(size_t)NROWS * EE];
__device__ __half g_ench[(size_t)NROWS * EE];
__device__ __half g_po1h[(size_t)NROWS * EE];
__device__ __half g_po2h[(size_t)NROWS * EE];
__device__ __half g_bufh[(size_t)NROWS * EE];
// fp16 weights, transposed to [out][in]
__device__ __half g_wqkvh[3 * EE * EE];
__device__ __half g_wq2h[EE * EE];
__device__ __half g_wkvh[2 * EE * EE];
__device__ __half g_wp1h[EE * EE];
__device__ __half g_wp2h[EE * EE];
__device__ __half g_wf1h[FFD * EE];
__device__ __half g_wf2h[EE * FFD];
__device__ float  g_bqkv[3 * EE];
__device__ float  g_bkv[2 * EE];
__device__ float  g_bq2[EE];

// ---------------- PTX helpers ----------------------------------------------
__device__ __forceinline__ uint32_t smem_u32(const void* p) {
    uint32_t a;
    asm("{ .reg .u64 t; cvta.to.shared.u64 t, %1; cvt.u32.u64 %0, t; }" : "=r"(a) : "l"(p));
    return a;
}
__device__ __forceinline__ void cp16(uint32_t dst, const void* src) {
    asm volatile("cp.async.cg.shared.global [%0], [%1], 16;" :: "r"(dst), "l"(src));
}
__device__ __forceinline__ void ldsm4(uint32_t& r0, uint32_t& r1, uint32_t& r2, uint32_t& r3,
                                      uint32_t addr) {
    asm volatile("ldmatrix.sync.aligned.m8n8.x4.shared.b16 {%0,%1,%2,%3}, [%4];"
                 : "=r"(r0), "=r"(r1), "=r"(r2), "=r"(r3) : "r"(addr));
}
__device__ __forceinline__ void ldsm4t(uint32_t& r0, uint32_t& r1, uint32_t& r2, uint32_t& r3,
                                       uint32_t addr) {
    asm volatile("ldmatrix.sync.aligned.m8n8.x4.trans.shared.b16 {%0,%1,%2,%3}, [%4];"
                 : "=r"(r0), "=r"(r1), "=r"(r2), "=r"(r3) : "r"(addr));
}
__device__ __forceinline__ void mma16816(float* c, const uint32_t* a, const uint32_t* b) {
    asm volatile(
        "mma.sync.aligned.m16n8k16.row.col.f32.f16.f16.f32 "
        "{%0,%1,%2,%3}, {%4,%5,%6,%7}, {%8,%9}, {%0,%1,%2,%3};"
        : "+f"(c[0]), "+f"(c[1]), "+f"(c[2]), "+f"(c[3])
        : "r"(a[0]), "r"(a[1]), "r"(a[2]), "r"(a[3]), "r"(b[0]), "r"(b[1]));
}
__device__ __forceinline__ uint32_t ph2(float a, float b) {
    __half2 h = __floats2half2_rn(a, b);
    return *reinterpret_cast<uint32_t*>(&h);
}
__device__ __forceinline__ uint32_t sw_off(int r, int seg) {
    return (uint32_t)(r * 128 + (((seg ^ (r & 7)) & 7) << 4));
}

// ---------------- shared 32x32 transpose tile -------------------------------
__device__ __forceinline__ void transpose32(const float* __restrict__ src, int lds,
                                            __half* __restrict__ dst, int ldd,
                                            int r0, int c0, float scale, int tid) {
    __shared__ float ttile[32][33];
    int tx = tid & 31, ty = tid >> 5;
#pragma unroll
    for (int i = 0; i < 4; i++) {
        int row = ty + i * 8;
        ttile[row][tx] = src[(size_t)(r0 + row) * lds + c0 + tx] * scale;
    }
    __syncthreads();
#pragma unroll
    for (int i = 0; i < 4; i++) {
        int row = ty + i * 8;
        dst[(size_t)(c0 + row) * ldd + r0 + tx] = __float2half_rn(ttile[tx][row]);
    }
}

// ---------------- packA: critical path -------------------------------------
#define PA_T   720
#define PA_B   (PA_T + 9)
#define NACTV  ((long long)((size_t)NROWS * EE / 4))
#define PA_TOTAL (PA_B + 12288)

__global__ void __launch_bounds__(256)
packA_kernel(
    const float* __restrict__ wq1, const float* __restrict__ wk1, const float* __restrict__ wv1,
    const float* __restrict__ wk2, const float* __restrict__ wv2,
    const float* __restrict__ bq1, const float* __restrict__ bk1, const float* __restrict__ bv1,
    const float* __restrict__ bq2, const float* __restrict__ bk2, const float* __restrict__ bv2,
    const float* __restrict__ x, const float* __restrict__ enc,
    __half* __restrict__ wqkv, __half* __restrict__ wkv,
    float* __restrict__ bqkv, float* __restrict__ bkv, float* __restrict__ bq2o,
    __half* __restrict__ xh, __half* __restrict__ ench)
{
    int bid = blockIdx.x, tid = threadIdx.x;
    if (bid < PA_T) {
        int tensor = bid / 144, rem = bid % 144;
        int h = rem / 24, t = rem % 24;
        int r0 = (t >> 1) * 32, c0 = (t & 1) * 32;
        const float* srcs[5] = {wq1, wk1, wv1, wk2, wv2};
        const float* src = srcs[tensor] + (size_t)h * EE * HSS;
        __half* dst; int rowoff;
        if (tensor < 3) { dst = wqkv; rowoff = tensor * EE; }
        else            { dst = wkv;  rowoff = (tensor - 3) * EE; }
        dst += (size_t)(rowoff + h * HSS) * EE;
        float scale = (tensor == 0) ? rsqrtf((float)EE) : 1.0f;
        transpose32(src, HSS, dst, EE, r0, c0, scale, tid);
        return;
    }
    if (bid < PA_B) {
        int i = (bid - PA_T) * 256 + tid;
        float scale = rsqrtf((float)EE);
        if (i < 3 * EE) {
            int sub = i / EE, jj = i % EE;
            bqkv[i] = sub == 0 ? bq1[jj] * scale : sub == 1 ? bk1[jj] : bv1[jj];
        } else if (i < 5 * EE) {
            int k = i - 3 * EE;
            bkv[k] = k < EE ? bk2[k] : bv2[k - EE];
        } else {
            int k = i - 5 * EE;
            bq2o[k] = bq2[k] * scale;
        }
        return;
    }
    long long ai = (long long)(bid - PA_B) * 256 + tid;
    const float* srcf; __half* dsth;
    if (ai < NACTV) { srcf = x; dsth = xh; }
    else { ai -= NACTV; srcf = enc; dsth = ench; }
    float4 v4 = ((const float4*)srcf)[ai];
    ((__half2*)dsth)[2 * ai]     = __floats2half2_rn(v4.x, v4.y);
    ((__half2*)dsth)[2 * ai + 1] = __floats2half2_rn(v4.z, v4.w);
}

// ---------------- packB: off-critical-path weight transposes ----------------
#define PB_WQ2 144
#define PB_PW  (PB_WQ2 + 288)
#define PB_F1  (PB_PW + 576)
#define PB_TOTAL (PB_F1 + 576)

__global__ void __launch_bounds__(256)
packB_kernel(const float* __restrict__ wq2,
             const float* __restrict__ pw1, const float* __restrict__ pw2,
             const float* __restrict__ fw1, const float* __restrict__ fw2,
             __half* __restrict__ wqo, __half* __restrict__ wp1o, __half* __restrict__ wp2o,
             __half* __restrict__ wf1o, __half* __restrict__ wf2o)
{
    int bid = blockIdx.x, tid = threadIdx.x;
    if (bid < PB_WQ2) {
        int h = bid / 24, t = bid % 24;
        int r0 = (t >> 1) * 32, c0 = (t & 1) * 32;
        transpose32(wq2 + (size_t)h * EE * HSS, HSS,
                    wqo + (size_t)(h * HSS) * EE, EE,
                    r0, c0, rsqrtf((float)EE), tid);
    } else if (bid < PB_PW) {
        int j = bid - PB_WQ2, which = j / 144, t = j % 144;
        int r0 = (t / 12) * 32, c0 = (t % 12) * 32;
        transpose32(which ? pw2 : pw1, EE, which ? wp2o : wp1o, EE, r0, c0, 1.0f, tid);
    } else if (bid < PB_F1) {
        int t = bid - PB_PW;
        int r0 = (t / 48) * 32, c0 = (t % 48) * 32;
        transpose32(fw1, FFD, wf1o, EE, r0, c0, 1.0f, tid);
    } else {
        int t = bid - PB_F1;
        int r0 = (t / 12) * 32, c0 = (t % 12) * 32;
        transpose32(fw2, EE, wf2o, FFD, r0, c0, 1.0f, tid);
    }
}

// ---------------- fp16 tensor-core GEMM mainloop (128x128, BK=64) -----------
#define G16_SMEM (3 * 32768)

template <int K>
__device__ __forceinline__ void load_chunk(uint32_t sbase,
                                           const __half* __restrict__ A,
                                           const __half* __restrict__ Wt,
                                           int row0, int col0, int tid,
                                           int stage, int kt) {
    uint32_t sA = sbase + (uint32_t)stage * 32768u;
    uint32_t sB = sA + 16384u;
#pragma unroll
    for (int i = 0; i < 4; i++) {
        int li = tid + i * 256; int r = li >> 3, sg = li & 7;
        cp16(sA + sw_off(r, sg), A + (size_t)(row0 + r) * K + kt + sg * 8);
        cp16(sB + sw_off(r, sg), Wt + (size_t)(col0 + r) * K + kt + sg * 8);
    }
    asm volatile("cp.async.commit_group;");
}

template <int K>
__device__ __forceinline__ void gemm_mainloop(float acc[4][4][4],
                                              const __half* __restrict__ A,
                                              const __half* __restrict__ Wt,
                                              int row0, int col0, int tid,
                                              int wm, int wn, int j, int rr,
                                              uint32_t sbase)
{
    constexpr int nch = K >> 6;
    load_chunk<K>(sbase, A, Wt, row0, col0, tid, 0, 0);
    load_chunk<K>(sbase, A, Wt, row0, col0, tid, 1, 64);
#pragma unroll 2
    for (int it = 0; it < nch; it++) {
        if (it + 1 < nch) asm volatile("cp.async.wait_group 1;");
        else              asm volatile("cp.async.wait_group 0;");
        __syncthreads();
        if (it + 2 < nch)
            load_chunk<K>(sbase, A, Wt, row0, col0, tid, (it + 2) % 3, (it + 2) * 64);
        uint32_t sA = sbase + (uint32_t)(it % 3) * 32768u;
        uint32_t sB = sA + 16384u;
#pragma unroll
        for (int ks = 0; ks < 4; ks++) {
            uint32_t a[4][4], bfr[2][4];
#pragma unroll
            for (int mt = 0; mt < 4; mt++)
                ldsm4(a[mt][0], a[mt][1], a[mt][2], a[mt][3],
                      sA + sw_off(wm * 64 + mt * 16 + (j & 1) * 8 + rr, ks * 2 + (j >> 1)));
#pragma unroll
            for (int p = 0; p < 2; p++)
                ldsm4(bfr[p][0], bfr[p][1], bfr[p][2], bfr[p][3],
                      sB + sw_off(wn * 32 + p * 16 + (j >> 1) * 8 + rr, ks * 2 + (j & 1)));
#pragma unroll
            for (int mt = 0; mt < 4; mt++)
#pragma unroll
                for (int nt = 0; nt < 4; nt++)
                    mma16816(acc[mt][nt], a[mt], &bfr[nt >> 1][(nt & 1) * 2]);
        }
    }
}

// ---------------- plain GEMM (bias, opt resid/relu, fp16 out) ---------------
template <int K>
__global__ void __launch_bounds__(256, 2)
gemm_std(const __half* __restrict__ A, const __half* __restrict__ Wt,
         const float* __restrict__ bias, const __half* __restrict__ resid,
         __half* __restrict__ Ch, int M, int relu)
{
    extern __shared__ char gsm[];
    uint32_t sbase = smem_u32(gsm);
    int tid = threadIdx.x, lane = tid & 31, warp = tid >> 5;
    int wm = warp >> 2, wn = warp & 3;
    int gid = lane >> 2, tg = lane & 3;
    int j = lane >> 3, rr = lane & 7;
    int col0 = blockIdx.x * 128, row0 = blockIdx.y * 128;

    float acc[4][4][4];
#pragma unroll
    for (int a = 0; a < 4; a++)
#pragma unroll
        for (int b = 0; b < 4; b++)
#pragma unroll
            for (int c = 0; c < 4; c++) acc[a][b][c] = 0.0f;

    gemm_mainloop<K>(acc, A, Wt, row0, col0, tid, wm, wn, j, rr, sbase);

#pragma unroll
    for (int mt = 0; mt < 4; mt++)
#pragma unroll
        for (int nt = 0; nt < 4; nt++) {
            int r0 = row0 + wm * 64 + mt * 16 + gid;
            int c0 = col0 + wn * 32 + nt * 8 + tg * 2;
            float b0 = bias[c0], b1 = bias[c0 + 1];
            float v0 = acc[mt][nt][0] + b0, v1 = acc[mt][nt][1] + b1;
            float v2 = acc[mt][nt][2] + b0, v3 = acc[mt][nt][3] + b1;
            if (resid) {
                float2 ra = __half22float2(*(const __half2*)(resid + (size_t)r0 * M + c0));
                float2 rb = __half22float2(*(const __half2*)(resid + (size_t)(r0 + 8) * M + c0));
                v0 += ra.x; v1 += ra.y; v2 += rb.x; v3 += rb.y;
            }
            if (relu) {
                v0 = fmaxf(v0, 0.f); v1 = fmaxf(v1, 0.f);
                v2 = fmaxf(v2, 0.f); v3 = fmaxf(v3, 0.f);
            }
            *(__half2*)(Ch + (size_t)r0 * M + c0)       = __floats2half2_rn(v0, v1);
            *(__half2*)(Ch + (size_t)(r0 + 8) * M + c0) = __floats2half2_rn(v2, v3);
        }
}

// ---------------- fused GEMM + residual + LayerNorm (3-CTA cluster) ---------
// Used for the FINAL stage only (K=1536, fp32 out).
template <int K, bool F32OUT>
__global__ void __launch_bounds__(256, 2) __cluster_dims__(3, 1, 1)
gemm_ln(const __half* __restrict__ A, const __half* __restrict__ Wt,
        const float* __restrict__ bias, const __half* __restrict__ resid,
        const float* __restrict__ lng, const float* __restrict__ lnb,
        __half* __restrict__ Oh, float* __restrict__ Of)
{
    extern __shared__ char gsm[];
    __shared__ float s_sum[128], s_sq[128], s_mean[128], s_inv[128];
    uint32_t sbase = smem_u32(gsm);
    int tid = threadIdx.x, lane = tid & 31, warp = tid >> 5;
    int wm = warp >> 2, wn = warp & 3;
    int gid = lane >> 2, tg = lane & 3;
    int j = lane >> 3, rr = lane & 7;
    int col0 = blockIdx.x * 128, row0 = blockIdx.y * 128;
    const int M = 384;

    if (tid < 128) { s_sum[tid] = 0.0f; s_sq[tid] = 0.0f; }

    float acc[4][4][4];
#pragma unroll
    for (int a = 0; a < 4; a++)
#pragma unroll
        for (int b = 0; b < 4; b++)
#pragma unroll
            for (int c = 0; c < 4; c++) acc[a][b][c] = 0.0f;

    gemm_mainloop<K>(acc, A, Wt, row0, col0, tid, wm, wn, j, rr, sbase);

#pragma unroll
    for (int mt = 0; mt < 4; mt++) {
        int r0 = row0 + wm * 64 + mt * 16 + gid;
        float ps0 = 0.f, sq0 = 0.f, ps1 = 0.f, sq1 = 0.f;
#pragma unroll
        for (int nt = 0; nt < 4; nt++) {
            int c0 = col0 + wn * 32 + nt * 8 + tg * 2;
            float b0 = bias[c0], b1 = bias[c0 + 1];
            float2 ra = __half22float2(*(const __half2*)(resid + (size_t)r0 * M + c0));
            float2 rb = __half22float2(*(const __half2*)(resid + (size_t)(r0 + 8) * M + c0));
            float v0 = acc[mt][nt][0] + b0 + ra.x;
            float v1 = acc[mt][nt][1] + b1 + ra.y;
            float v2 = acc[mt][nt][2] + b0 + rb.x;
            float v3 = acc[mt][nt][3] + b1 + rb.y;
            acc[mt][nt][0] = v0; acc[mt][nt][1] = v1;
            acc[mt][nt][2] = v2; acc[mt][nt][3] = v3;
            ps0 += v0 + v1; sq0 += v0 * v0 + v1 * v1;
            ps1 += v2 + v3; sq1 += v2 * v2 + v3 * v3;
        }
        ps0 += __shfl_xor_sync(~0u, ps0, 1); ps0 += __shfl_xor_sync(~0u, ps0, 2);
        sq0 += __shfl_xor_sync(~0u, sq0, 1); sq0 += __shfl_xor_sync(~0u, sq0, 2);
        ps1 += __shfl_xor_sync(~0u, ps1, 1); ps1 += __shfl_xor_sync(~0u, ps1, 2);
        sq1 += __shfl_xor_sync(~0u, sq1, 1); sq1 += __shfl_xor_sync(~0u, sq1, 2);
        if (tg == 0) {
            int rl = wm * 64 + mt * 16 + gid;
            atomicAdd(&s_sum[rl], ps0); atomicAdd(&s_sq[rl], sq0);
            atomicAdd(&s_sum[rl + 8], ps1); atomicAdd(&s_sq[rl + 8], sq1);
        }
    }

    cg::cluster_group cluster = cg::this_cluster();
    cluster.sync();
    if (tid < 128) {
        float ssum = 0.f, ssq = 0.f;
#pragma unroll
        for (int rk = 0; rk < 3; rk++) {
            const float* psu = cluster.map_shared_rank(s_sum, rk);
            const float* psq = cluster.map_shared_rank(s_sq, rk);
            ssum += psu[tid]; ssq += psq[tid];
        }
        float mean = ssum * (1.0f / EE);
        float var = ssq * (1.0f / EE) - mean * mean;
        s_mean[tid] = mean;
        s_inv[tid] = rsqrtf(var + 1e-5f);
    }
    cluster.sync();

#pragma unroll
    for (int mt = 0; mt < 4; mt++) {
        int rl = wm * 64 + mt * 16 + gid;
        int r0 = row0 + rl;
        float m0 = s_mean[rl],     i0 = s_inv[rl];
        float m1 = s_mean[rl + 8], i1 = s_inv[rl + 8];
#pragma unroll
        for (int nt = 0; nt < 4; nt++) {
            int c0 = col0 + wn * 32 + nt * 8 + tg * 2;
            float g0 = lng[c0], g1 = lng[c0 + 1];
            float bb0 = lnb[c0], bb1 = lnb[c0 + 1];
            float v0 = (acc[mt][nt][0] - m0) * i0 * g0 + bb0;
            float v1 = (acc[mt][nt][1] - m0) * i0 * g1 + bb1;
            float v2 = (acc[mt][nt][2] - m1) * i1 * g0 + bb0;
            float v3 = (acc[mt][nt][3] - m1) * i1 * g1 + bb1;
            if (F32OUT) {
                *(float2*)(Of + (size_t)r0 * M + c0)       = make_float2(v0, v1);
                *(float2*)(Of + (size_t)(r0 + 8) * M + c0) = make_float2(v2, v3);
            } else {
                *(__half2*)(Oh + (size_t)r0 * M + c0)       = __floats2half2_rn(v0, v1);
                *(__half2*)(Oh + (size_t)(r0 + 8) * M + c0) = __floats2half2_rn(v2, v3);
            }
        }
    }
}

// ---------------- flash attention: 128 q-rows per CTA, 8 warps --------------
#define AT_SMEM (16384 + 2 * 16384)

__global__ void __launch_bounds__(256, 2)
attn16_kernel(const __half* __restrict__ Qg, int ldq,
              const __half* __restrict__ Kg, const __half* __restrict__ Vg, int ldkv,
              __half* __restrict__ Og)
{
    extern __shared__ __align__(128) char asmem[];
    uint32_t sbase = smem_u32(asmem);
    uint32_t sQ = sbase;
    int tid = threadIdx.x, lane = tid & 31, w = tid >> 5;
    int gid = lane >> 2, tg = lane & 3;
    int j = lane >> 3, rr = lane & 7;

    int bid = blockIdx.x;
    int qt = (bid & 1) ^ 1;
    int h = (bid >> 1) % HH, b = bid / (2 * HH);
    int t0 = qt * 128;
    int hoff = h * HSS;

    const __half* qrow = Qg + (size_t)(b * TT + t0) * ldq + hoff;
#pragma unroll
    for (int i = 0; i < 4; i++) {
        int li = tid + i * 256; int r = li >> 3, sg = li & 7;
        cp16(sQ + sw_off(r, sg), qrow + (size_t)r * ldq + sg * 8);
    }
#define KVLOAD(ut, bufi)                                                           \
    {                                                                              \
        uint32_t sK_ = sbase + 16384u + (uint32_t)(bufi) * 16384u;                 \
        uint32_t sV_ = sK_ + 8192u;                                                \
        const __half* kr = Kg + (size_t)(b * TT + (ut) * 64) * ldkv + hoff;        \
        const __half* vr = Vg + (size_t)(b * TT + (ut) * 64) * ldkv + hoff;        \
        _Pragma("unroll")                                                          \
        for (int i = 0; i < 2; i++) {                                              \
            int li = tid + i * 256; int r = li >> 3, sg = li & 7;                  \
            cp16(sK_ + sw_off(r, sg), kr + (size_t)r * ldkv + sg * 8);             \
            cp16(sV_ + sw_off(r, sg), vr + (size_t)r * ldkv + sg * 8);             \
        }                                                                          \
        asm volatile("cp.async.commit_group;");                                    \
    }
    KVLOAD(0, 0);
    asm volatile("cp.async.wait_group 0;");
    __syncthreads();

    uint32_t qf[4][4];
#pragma unroll
    for (int ks = 0; ks < 4; ks++)
        ldsm4(qf[ks][0], qf[ks][1], qf[ks][2], qf[ks][3],
              sQ + sw_off(w * 16 + (j & 1) * 8 + rr, ks * 2 + (j >> 1)));

    float o[8][4];
#pragma unroll
    for (int nt = 0; nt < 8; nt++)
#pragma unroll
        for (int e = 0; e < 4; e++) o[nt][e] = 0.0f;
    float m0 = -1e30f, m1 = -1e30f, l0 = 0.0f, l1 = 0.0f;

    int nkv = 2 * (qt + 1);
    int r0g = t0 + w * 16 + gid;
    for (int ut = 0; ut < nkv; ut++) {
        if (ut > 0) { asm volatile("cp.async.wait_group 0;"); __syncthreads(); }
        if (ut < nkv - 1) KVLOAD(ut + 1, (ut + 1) & 1);
        uint32_t sK = sbase + 16384u + (uint32_t)(ut & 1) * 16384u;
        uint32_t sV = sK + 8192u;

        float s[8][4];
#pragma unroll
        for (int nt = 0; nt < 8; nt++)
#pragma unroll
            for (int e = 0; e < 4; e++) s[nt][e] = 0.0f;
#pragma unroll
        for (int ks = 0; ks < 4; ks++) {
            uint32_t kb[4][4];
#pragma unroll
            for (int p = 0; p < 4; p++)
                ldsm4(kb[p][0], kb[p][1], kb[p][2], kb[p][3],
                      sK + sw_off(p * 16 + (j >> 1) * 8 + rr, ks * 2 + (j & 1)));
#pragma unroll
            for (int nt = 0; nt < 8; nt++)
                mma16816(s[nt], qf[ks], &kb[nt >> 1][(nt & 1) * 2]);
        }
        if (ut >= 2 * qt) {
#pragma unroll
            for (int nt = 0; nt < 8; nt++) {
                int u0 = ut * 64 + nt * 8 + tg * 2;
                if (u0     > r0g)     s[nt][0] = -1e30f;
                if (u0 + 1 > r0g)     s[nt][1] = -1e30f;
                if (u0     > r0g + 8) s[nt][2] = -1e30f;
                if (u0 + 1 > r0g + 8) s[nt][3] = -1e30f;
            }
        }
        float mx0 = -1e30f, mx1 = -1e30f;
#pragma unroll
        for (int nt = 0; nt < 8; nt++) {
            mx0 = fmaxf(mx0, fmaxf(s[nt][0], s[nt][1]));
            mx1 = fmaxf(mx1, fmaxf(s[nt][2], s[nt][3]));
        }
        mx0 = fmaxf(mx0, __shfl_xor_sync(~0u, mx0, 1));
        mx0 = fmaxf(mx0, __shfl_xor_sync(~0u, mx0, 2));
        mx1 = fmaxf(mx1, __shfl_xor_sync(~0u, mx1, 1));
        mx1 = fmaxf(mx1, __shfl_xor_sync(~0u, mx1, 2));
        float mn0 = fmaxf(m0, mx0), mn1 = fmaxf(m1, mx1);
        float f0 = __expf(m0 - mn0), f1 = __expf(m1 - mn1);
        m0 = mn0; m1 = mn1;
        float rs0 = 0.0f, rs1 = 0.0f;
#pragma unroll
        for (int nt = 0; nt < 8; nt++) {
            s[nt][0] = __expf(s[nt][0] - mn0); rs0 += s[nt][0];
            s[nt][1] = __expf(s[nt][1] - mn0); rs0 += s[nt][1];
            s[nt][2] = __expf(s[nt][2] - mn1); rs1 += s[nt][2];
            s[nt][3] = __expf(s[nt][3] - mn1); rs1 += s[nt][3];
        }
        rs0 += __shfl_xor_sync(~0u, rs0, 1); rs0 += __shfl_xor_sync(~0u, rs0, 2);
        rs1 += __shfl_xor_sync(~0u, rs1, 1); rs1 += __shfl_xor_sync(~0u, rs1, 2);
        l0 = l0 * f0 + rs0;
        l1 = l1 * f1 + rs1;
#pragma unroll
        for (int nt = 0; nt < 8; nt++) {
            o[nt][0] *= f0; o[nt][1] *= f0; o[nt][2] *= f1; o[nt][3] *= f1;
        }
        uint32_t pa[4][4];
#pragma unroll
        for (int kk = 0; kk < 4; kk++) {
            pa[kk][0] = ph2(s[2 * kk][0], s[2 * kk][1]);
            pa[kk][1] = ph2(s[2 * kk][2], s[2 * kk][3]);
            pa[kk][2] = ph2(s[2 * kk + 1][0], s[2 * kk + 1][1]);
            pa[kk][3] = ph2(s[2 * kk + 1][2], s[2 * kk + 1][3]);
        }
#pragma unroll
        for (int kk = 0; kk < 4; kk++) {
            uint32_t vb[4][4];
#pragma unroll
            for (int p = 0; p < 4; p++)
                ldsm4t(vb[p][0], vb[p][1], vb[p][2], vb[p][3],
                       sV + sw_off(kk * 16 + (j & 1) * 8 + rr, p * 2 + (j >> 1)));
#pragma unroll
            for (int nt = 0; nt < 8; nt++)
                mma16816(o[nt], pa[kk], &vb[nt >> 1][(nt & 1) * 2]);
        }
    }
    float i0 = 1.0f / l0, i1 = 1.0f / l1;
    __half* orow = Og + (size_t)(b * TT + t0) * EE + hoff;
#pragma unroll
    for (int nt = 0; nt < 8; nt++) {
        int c = nt * 8 + tg * 2;
        *(__half2*)(orow + (size_t)(w * 16 + gid) * EE + c) =
            __floats2half2_rn(o[nt][0] * i0, o[nt][1] * i0);
        *(__half2*)(orow + (size_t)(w * 16 + gid + 8) * EE + c) =
            __floats2half2_rn(o[nt][2] * i1, o[nt][3] * i1);
    }
}

// ---------------- LayerNorm: fp16 in, one warp per row, 16 rows/CTA ---------
__global__ void __launch_bounds__(512)
ln_kernel(const __half* __restrict__ s_in,
          const float* __restrict__ g, const float* __restrict__ bt,
          __half* __restrict__ oh) {
    int warp = threadIdx.x >> 5, lane = threadIdx.x & 31;
    int row = blockIdx.x * 16 + warp;
    const uint2* rp = (const uint2*)(s_in + (size_t)row * EE);
    float v[3][4];
#pragma unroll
    for (int i = 0; i < 3; i++) {
        uint2 raw = rp[lane + 32 * i];
        float2 f0 = __half22float2(*reinterpret_cast<__half2*>(&raw.x));
        float2 f1 = __half22float2(*reinterpret_cast<__half2*>(&raw.y));
        v[i][0] = f0.x; v[i][1] = f0.y; v[i][2] = f1.x; v[i][3] = f1.y;
    }
    float s = 0.0f;
#pragma unroll
    for (int i = 0; i < 3; i++) s += v[i][0] + v[i][1] + v[i][2] + v[i][3];
#pragma unroll
    for (int off = 16; off; off >>= 1) s += __shfl_xor_sync(~0u, s, off);
    float mean = s * (1.0f / EE);
    float sq = 0.0f;
#pragma unroll
    for (int i = 0; i < 3; i++) {
        float a0 = v[i][0] - mean, a1 = v[i][1] - mean;
        float a2 = v[i][2] - mean, a3 = v[i][3] - mean;
        sq += a0 * a0 + a1 * a1 + a2 * a2 + a3 * a3;
    }
#pragma unroll
    for (int off = 16; off; off >>= 1) sq += __shfl_xor_sync(~0u, sq, off);
    float inv = rsqrtf(sq * (1.0f / EE) + 1e-5f);
    uint2* ohp = (uint2*)(oh + (size_t)row * EE);
#pragma unroll
    for (int i = 0; i < 3; i++) {
        int e4 = lane + 32 * i;
        float4 gg = *(const float4*)(g + e4 * 4);
        float4 bb = *(const float4*)(bt + e4 * 4);
        float r0 = (v[i][0] - mean) * inv * gg.x + bb.x;
        float r1 = (v[i][1] - mean) * inv * gg.y + bb.y;
        float r2 = (v[i][2] - mean) * inv * gg.z + bb.z;
        float r3 = (v[i][3] - mean) * inv * gg.w + bb.w;
        uint2 pk;
        pk.x = ph2(r0, r1);
        pk.y = ph2(r2, r3);
        ohp[e4] = pk;
    }
}

// ---------------- host orchestration ---------------------------------------
extern "C" void kernel_launch(void* const* d_in, const int* in_sizes, int n_in,
                              void* d_out, int out_size) {
    const float* enc = (const float*)d_in[0];
    const float* x   = (const float*)d_in[1];
    const float* sa1_wq = (const float*)d_in[2];
    const float* sa1_bq = (const float*)d_in[3];
    const float* sa1_wk = (const float*)d_in[4];
    const float* sa1_bk = (const float*)d_in[5];
    const float* sa1_wv = (const float*)d_in[6];
    const float* sa1_bv = (const float*)d_in[7];
    const float* sa1_pw = (const float*)d_in[8];
    const float* sa1_pb = (const float*)d_in[9];
    const float* sa2_wq = (const float*)d_in[10];
    const float* sa2_bq = (const float*)d_in[11];
    const float* sa2_wk = (const float*)d_in[12];
    const float* sa2_bk = (const float*)d_in[13];
    const float* sa2_wv = (const float*)d_in[14];
    const float* sa2_bv = (const float*)d_in[15];
    const float* sa2_pw = (const float*)d_in[16];
    const float* sa2_pb = (const float*)d_in[17];
    const float* ff_w1  = (const float*)d_in[18];
    const float* ff_b1  = (const float*)d_in[19];
    const float* ff_w2  = (const float*)d_in[20];
    const float* ff_b2  = (const float*)d_in[21];
    const float* ln1_g  = (const float*)d_in[22];
    const float* ln1_b  = (const float*)d_in[23];
    const float* ln2_g  = (const float*)d_in[24];
    const float* ln2_b  = (const float*)d_in[25];
    const float* ln3_g  = (const float*)d_in[26];
    const float* ln3_b  = (const float*)d_in[27];
    float* out = (float*)d_out;

    static cudaStream_t s_aux = nullptr;
    static cudaEvent_t evFork = nullptr, evActs = nullptr, evW = nullptr, evKV = nullptr;
    if (!s_aux) {
        cudaStreamCreateWithFlags(&s_aux, cudaStreamNonBlocking);
        cudaEventCreateWithFlags(&evFork, cudaEventDisableTiming);
        cudaEventCreateWithFlags(&evActs, cudaEventDisableTiming);
        cudaEventCreateWithFlags(&evW,    cudaEventDisableTiming);
        cudaEventCreateWithFlags(&evKV,   cudaEventDisableTiming);
        cudaFuncSetAttribute(gemm_std<384>,
                             cudaFuncAttributeMaxDynamicSharedMemorySize, G16_SMEM);
        cudaFuncSetAttribute(gemm_std<1536>,
                             cudaFuncAttributeMaxDynamicSharedMemorySize, G16_SMEM);
        cudaFuncSetAttribute(gemm_ln<1536, true>,
                             cudaFuncAttributeMaxDynamicSharedMemorySize, G16_SMEM);
        cudaFuncSetAttribute(attn16_kernel,
                             cudaFuncAttributeMaxDynamicSharedMemorySize, AT_SMEM);
    }

    __half *pqkv, *pkv, *pq, *patt, *phid, *pxh, *pench, *po1h, *po2h, *pbufh;
    __half *pwqkv, *pwq2, *pwkv, *pwp1, *pwp2, *pwf1, *pwf2;
    float *pbqkv, *pbkv, *pbq2;
    cudaGetSymbolAddress((void**)&pqkv,  g_qkv_h);
    cudaGetSymbolAddress((void**)&pkv,   g_kv_h);
    cudaGetSymbolAddress((void**)&pq,    g_q_h);
    cudaGetSymbolAddress((void**)&patt,  g_att_h);
    cudaGetSymbolAddress((void**)&phid,  g_hid_h);
    cudaGetSymbolAddress((void**)&pxh,   g_xh);
    cudaGetSymbolAddress((void**)&pench, g_ench);
    cudaGetSymbolAddress((void**)&po1h,  g_po1h);
    cudaGetSymbolAddress((void**)&po2h,  g_po2h);
    cudaGetSymbolAddress((void**)&pbufh, g_bufh);
    cudaGetSymbolAddress((void**)&pwqkv, g_wqkvh);
    cudaGetSymbolAddress((void**)&pwq2,  g_wq2h);
    cudaGetSymbolAddress((void**)&pwkv,  g_wkvh);
    cudaGetSymbolAddress((void**)&pwp1,  g_wp1h);
    cudaGetSymbolAddress((void**)&pwp2,  g_wp2h);
    cudaGetSymbolAddress((void**)&pwf1,  g_wf1h);
    cudaGetSymbolAddress((void**)&pwf2,  g_wf2h);
    cudaGetSymbolAddress((void**)&pbqkv, g_bqkv);
    cudaGetSymbolAddress((void**)&pbkv,  g_bkv);
    cudaGetSymbolAddress((void**)&pbq2,  g_bq2);

    cudaEventRecord(evFork, 0);
    cudaStreamWaitEvent(s_aux, evFork, 0);

    packB_kernel<<<PB_TOTAL, 256, 0, s_aux>>>(
        sa2_wq, sa1_pw, sa2_pw, ff_w1, ff_w2,
        pwq2, pwp1, pwp2, pwf1, pwf2);
    cudaEventRecord(evW, s_aux);

    packA_kernel<<<PA_TOTAL, 256>>>(
        sa1_wq, sa1_wk, sa1_wv, sa2_wk, sa2_wv,
        sa1_bq, sa1_bk, sa1_bv, sa2_bq, sa2_bk, sa2_bv,
        x, enc,
        pwqkv, pwkv, pbqkv, pbkv, pbq2, pxh, pench);
    cudaEventRecord(evActs, 0);

    cudaStreamWaitEvent(s_aux, evActs, 0);
    gemm_std<384><<<dim3(6, 128), 256, G16_SMEM, s_aux>>>(
        pench, pwkv, pbkv, nullptr, pkv, 2 * EE, 0);
    cudaEventRecord(evKV, s_aux);

    gemm_std<384><<<dim3(9, 128), 256, G16_SMEM>>>(
        pxh, pwqkv, pbqkv, nullptr, pqkv, 3 * EE, 0);
    attn16_kernel<<<BB * HH * 2, 256, AT_SMEM>>>(pqkv, 3 * EE,
                                                 pqkv + EE, pqkv + 2 * EE, 3 * EE, patt);

    cudaStreamWaitEvent(0, evW, 0);
    gemm_std<384><<<dim3(3, 128), 256, G16_SMEM>>>(
        patt, pwp1, sa1_pb, pxh, pbufh, EE, 0);                 // bufh = x + proj
    ln_kernel<<<NROWS / 16, 512>>>(pbufh, ln1_g, ln1_b, po1h);

    gemm_std<384><<<dim3(3, 128), 256, G16_SMEM>>>(
        po1h, pwq2, pbq2, nullptr, pq, EE, 0);
    cudaStreamWaitEvent(0, evKV, 0);
    attn16_kernel<<<BB * HH * 2, 256, AT_SMEM>>>(pq, EE,
                                                 pkv, pkv + EE, 2 * EE, patt);
    gemm_std<384><<<dim3(3, 128), 256, G16_SMEM>>>(
        patt, pwp2, sa2_pb, po1h, pbufh, EE, 0);                // bufh = o1 + proj
    ln_kernel<<<NROWS / 16, 512>>>(pbufh, ln2_g, ln2_b, po2h);

    gemm_std<384><<<dim3(12, 128), 256, G16_SMEM>>>(
        po2h, pwf1, ff_b1, nullptr, phid, FFD, 1);
    gemm_ln<1536, true><<<dim3(3, 128), 256, G16_SMEM>>>(
        phid, pwf2, ff_b2, po2h, ln3_g, ln3_b, nullptr, out);
}

// round 16
// speedup vs baseline: 1.0227x; 1.0108x over previous
#include <cuda_runtime.h>
#include <cuda_fp16.h>
#include <cooperative_groups.h>
#include <cstdint>
#include <cstddef>

namespace cg = cooperative_groups;

// Problem constants
#define EE   384
#define HH   6
#define HSS  64
#define BB   64
#define TT   256
#define FFD  1536
#define NROWS (BB*TT)          // 16384

// ---------------- scratch (device globals; no allocation allowed) ----------
__device__ __half g_qkv_h[(size_t)NROWS * 3 * EE];
__device__ __half g_kv_h[(size_t)NROWS * 2 * EE];
__device__ __half g_q_h[(size_t)NROWS * EE];
__device__ __half g_att_h[(size_t)NROWS * EE];
__device__ __half g_hid_h[(size_t)NROWS * FFD];
__device__ __half g_xh[(size_t)NROWS * EE];
__device__ __half g_ench[(size_t)NROWS * EE];
__device__ __half g_po1h[(size_t)NROWS * EE];
__device__ __half g_po2h[(size_t)NROWS * EE];
__device__ __half g_bufh[(size_t)NROWS * EE];
// fp16 weights, transposed to [out][in]
__device__ __half g_wqkvh[3 * EE * EE];
__device__ __half g_wq2h[EE * EE];
__device__ __half g_wkvh[2 * EE * EE];
__device__ __half g_wp1h[EE * EE];
__device__ __half g_wp2h[EE * EE];
__device__ __half g_wf1h[FFD * EE];
__device__ __half g_wf2h[EE * FFD];
__device__ float  g_bqkv[3 * EE];
__device__ float  g_bkv[2 * EE];
__device__ float  g_bq2[EE];

// ---------------- PTX helpers ----------------------------------------------
__device__ __forceinline__ uint32_t smem_u32(const void* p) {
    uint32_t a;
    asm("{ .reg .u64 t; cvta.to.shared.u64 t, %1; cvt.u32.u64 %0, t; }" : "=r"(a) : "l"(p));
    return a;
}
__device__ __forceinline__ void cp16(uint32_t dst, const void* src) {
    asm volatile("cp.async.cg.shared.global [%0], [%1], 16;" :: "r"(dst), "l"(src));
}
__device__ __forceinline__ void ldsm4(uint32_t& r0, uint32_t& r1, uint32_t& r2, uint32_t& r3,
                                      uint32_t addr) {
    asm volatile("ldmatrix.sync.aligned.m8n8.x4.shared.b16 {%0,%1,%2,%3}, [%4];"
                 : "=r"(r0), "=r"(r1), "=r"(r2), "=r"(r3) : "r"(addr));
}
__device__ __forceinline__ void ldsm4t(uint32_t& r0, uint32_t& r1, uint32_t& r2, uint32_t& r3,
                                       uint32_t addr) {
    asm volatile("ldmatrix.sync.aligned.m8n8.x4.trans.shared.b16 {%0,%1,%2,%3}, [%4];"
                 : "=r"(r0), "=r"(r1), "=r"(r2), "=r"(r3) : "r"(addr));
}
__device__ __forceinline__ void mma16816(float* c, const uint32_t* a, const uint32_t* b) {
    asm volatile(
        "mma.sync.aligned.m16n8k16.row.col.f32.f16.f16.f32 "
        "{%0,%1,%2,%3}, {%4,%5,%6,%7}, {%8,%9}, {%0,%1,%2,%3};"
        : "+f"(c[0]), "+f"(c[1]), "+f"(c[2]), "+f"(c[3])
        : "r"(a[0]), "r"(a[1]), "r"(a[2]), "r"(a[3]), "r"(b[0]), "r"(b[1]));
}
__device__ __forceinline__ uint32_t ph2(float a, float b) {
    __half2 h = __floats2half2_rn(a, b);
    return *reinterpret_cast<uint32_t*>(&h);
}
__device__ __forceinline__ uint32_t ex2_f16x2(uint32_t in) {
    uint32_t out;
    asm("ex2.approx.f16x2 %0, %1;" : "=r"(out) : "r"(in));
    return out;
}
__device__ __forceinline__ uint32_t sw_off(int r, int seg) {
    return (uint32_t)(r * 128 + (((seg ^ (r & 7)) & 7) << 4));
}

// ---------------- shared 32x32 transpose tile -------------------------------
__device__ __forceinline__ void transpose32(const float* __restrict__ src, int lds,
                                            __half* __restrict__ dst, int ldd,
                                            int r0, int c0, float scale, int tid) {
    __shared__ float ttile[32][33];
    int tx = tid & 31, ty = tid >> 5;
#pragma unroll
    for (int i = 0; i < 4; i++) {
        int row = ty + i * 8;
        ttile[row][tx] = src[(size_t)(r0 + row) * lds + c0 + tx] * scale;
    }
    __syncthreads();
#pragma unroll
    for (int i = 0; i < 4; i++) {
        int row = ty + i * 8;
        dst[(size_t)(c0 + row) * ldd + r0 + tx] = __float2half_rn(ttile[tx][row]);
    }
}

// ---------------- packA: critical path -------------------------------------
#define PA_T   720
#define PA_B   (PA_T + 9)
#define NACTV  ((long long)((size_t)NROWS * EE / 4))
#define PA_TOTAL (PA_B + 12288)

__global__ void __launch_bounds__(256)
packA_kernel(
    const float* __restrict__ wq1, const float* __restrict__ wk1, const float* __restrict__ wv1,
    const float* __restrict__ wk2, const float* __restrict__ wv2,
    const float* __restrict__ bq1, const float* __restrict__ bk1, const float* __restrict__ bv1,
    const float* __restrict__ bq2, const float* __restrict__ bk2, const float* __restrict__ bv2,
    const float* __restrict__ x, const float* __restrict__ enc,
    __half* __restrict__ wqkv, __half* __restrict__ wkv,
    float* __restrict__ bqkv, float* __restrict__ bkv, float* __restrict__ bq2o,
    __half* __restrict__ xh, __half* __restrict__ ench)
{
    int bid = blockIdx.x, tid = threadIdx.x;
    if (bid < PA_T) {
        int tensor = bid / 144, rem = bid % 144;
        int h = rem / 24, t = rem % 24;
        int r0 = (t >> 1) * 32, c0 = (t & 1) * 32;
        const float* srcs[5] = {wq1, wk1, wv1, wk2, wv2};
        const float* src = srcs[tensor] + (size_t)h * EE * HSS;
        __half* dst; int rowoff;
        if (tensor < 3) { dst = wqkv; rowoff = tensor * EE; }
        else            { dst = wkv;  rowoff = (tensor - 3) * EE; }
        dst += (size_t)(rowoff + h * HSS) * EE;
        float scale = (tensor == 0) ? rsqrtf((float)EE) : 1.0f;
        transpose32(src, HSS, dst, EE, r0, c0, scale, tid);
        return;
    }
    if (bid < PA_B) {
        int i = (bid - PA_T) * 256 + tid;
        float scale = rsqrtf((float)EE);
        if (i < 3 * EE) {
            int sub = i / EE, jj = i % EE;
            bqkv[i] = sub == 0 ? bq1[jj] * scale : sub == 1 ? bk1[jj] : bv1[jj];
        } else if (i < 5 * EE) {
            int k = i - 3 * EE;
            bkv[k] = k < EE ? bk2[k] : bv2[k - EE];
        } else {
            int k = i - 5 * EE;
            bq2o[k] = bq2[k] * scale;
        }
        return;
    }
    long long ai = (long long)(bid - PA_B) * 256 + tid;
    const float* srcf; __half* dsth;
    if (ai < NACTV) { srcf = x; dsth = xh; }
    else { ai -= NACTV; srcf = enc; dsth = ench; }
    float4 v4 = ((const float4*)srcf)[ai];
    ((__half2*)dsth)[2 * ai]     = __floats2half2_rn(v4.x, v4.y);
    ((__half2*)dsth)[2 * ai + 1] = __floats2half2_rn(v4.z, v4.w);
}

// ---------------- packB: off-critical-path weight transposes ----------------
#define PB_WQ2 144
#define PB_PW  (PB_WQ2 + 288)
#define PB_F1  (PB_PW + 576)
#define PB_TOTAL (PB_F1 + 576)

__global__ void __launch_bounds__(256)
packB_kernel(const float* __restrict__ wq2,
             const float* __restrict__ pw1, const float* __restrict__ pw2,
             const float* __restrict__ fw1, const float* __restrict__ fw2,
             __half* __restrict__ wqo, __half* __restrict__ wp1o, __half* __restrict__ wp2o,
             __half* __restrict__ wf1o, __half* __restrict__ wf2o)
{
    int bid = blockIdx.x, tid = threadIdx.x;
    if (bid < PB_WQ2) {
        int h = bid / 24, t = bid % 24;
        int r0 = (t >> 1) * 32, c0 = (t & 1) * 32;
        transpose32(wq2 + (size_t)h * EE * HSS, HSS,
                    wqo + (size_t)(h * HSS) * EE, EE,
                    r0, c0, rsqrtf((float)EE), tid);
    } else if (bid < PB_PW) {
        int j = bid - PB_WQ2, which = j / 144, t = j % 144;
        int r0 = (t / 12) * 32, c0 = (t % 12) * 32;
        transpose32(which ? pw2 : pw1, EE, which ? wp2o : wp1o, EE, r0, c0, 1.0f, tid);
    } else if (bid < PB_F1) {
        int t = bid - PB_PW;
        int r0 = (t / 48) * 32, c0 = (t % 48) * 32;
        transpose32(fw1, FFD, wf1o, EE, r0, c0, 1.0f, tid);
    } else {
        int t = bid - PB_F1;
        int r0 = (t / 12) * 32, c0 = (t % 12) * 32;
        transpose32(fw2, EE, wf2o, FFD, r0, c0, 1.0f, tid);
    }
}

// ---------------- fp16 tensor-core GEMM mainloop (128x128, BK=64) -----------
#define G16_SMEM (3 * 32768)

template <int K>
__device__ __forceinline__ void load_chunk(uint32_t sbase,
                                           const __half* __restrict__ A,
                                           const __half* __restrict__ Wt,
                                           int row0, int col0, int tid,
                                           int stage, int kt) {
    uint32_t sA = sbase + (uint32_t)stage * 32768u;
    uint32_t sB = sA + 16384u;
#pragma unroll
    for (int i = 0; i < 4; i++) {
        int li = tid + i * 256; int r = li >> 3, sg = li & 7;
        cp16(sA + sw_off(r, sg), A + (size_t)(row0 + r) * K + kt + sg * 8);
        cp16(sB + sw_off(r, sg), Wt + (size_t)(col0 + r) * K + kt + sg * 8);
    }
    asm volatile("cp.async.commit_group;");
}

template <int K>
__device__ __forceinline__ void gemm_mainloop(float acc[4][4][4],
                                              const __half* __restrict__ A,
                                              const __half* __restrict__ Wt,
                                              int row0, int col0, int tid,
                                              int wm, int wn, int j, int rr,
                                              uint32_t sbase)
{
    constexpr int nch = K >> 6;
    load_chunk<K>(sbase, A, Wt, row0, col0, tid, 0, 0);
    load_chunk<K>(sbase, A, Wt, row0, col0, tid, 1, 64);
#pragma unroll 2
    for (int it = 0; it < nch; it++) {
        if (it + 1 < nch) asm volatile("cp.async.wait_group 1;");
        else              asm volatile("cp.async.wait_group 0;");
        __syncthreads();
        if (it + 2 < nch)
            load_chunk<K>(sbase, A, Wt, row0, col0, tid, (it + 2) % 3, (it + 2) * 64);
        uint32_t sA = sbase + (uint32_t)(it % 3) * 32768u;
        uint32_t sB = sA + 16384u;
#pragma unroll
        for (int ks = 0; ks < 4; ks++) {
            uint32_t a[4][4], bfr[2][4];
#pragma unroll
            for (int mt = 0; mt < 4; mt++)
                ldsm4(a[mt][0], a[mt][1], a[mt][2], a[mt][3],
                      sA + sw_off(wm * 64 + mt * 16 + (j & 1) * 8 + rr, ks * 2 + (j >> 1)));
#pragma unroll
            for (int p = 0; p < 2; p++)
                ldsm4(bfr[p][0], bfr[p][1], bfr[p][2], bfr[p][3],
                      sB + sw_off(wn * 32 + p * 16 + (j >> 1) * 8 + rr, ks * 2 + (j & 1)));
#pragma unroll
            for (int mt = 0; mt < 4; mt++)
#pragma unroll
                for (int nt = 0; nt < 4; nt++)
                    mma16816(acc[mt][nt], a[mt], &bfr[nt >> 1][(nt & 1) * 2]);
        }
    }
}

// ---------------- plain GEMM (bias, opt resid/relu, fp16 out) ---------------
template <int K>
__global__ void __launch_bounds__(256, 2)
gemm_std(const __half* __restrict__ A, const __half* __restrict__ Wt,
         const float* __restrict__ bias, const __half* __restrict__ resid,
         __half* __restrict__ Ch, int M, int relu)
{
    extern __shared__ char gsm[];
    uint32_t sbase = smem_u32(gsm);
    int tid = threadIdx.x, lane = tid & 31, warp = tid >> 5;
    int wm = warp >> 2, wn = warp & 3;
    int gid = lane >> 2, tg = lane & 3;
    int j = lane >> 3, rr = lane & 7;
    int col0 = blockIdx.x * 128, row0 = blockIdx.y * 128;

    float acc[4][4][4];
#pragma unroll
    for (int a = 0; a < 4; a++)
#pragma unroll
        for (int b = 0; b < 4; b++)
#pragma unroll
            for (int c = 0; c < 4; c++) acc[a][b][c] = 0.0f;

    gemm_mainloop<K>(acc, A, Wt, row0, col0, tid, wm, wn, j, rr, sbase);

#pragma unroll
    for (int mt = 0; mt < 4; mt++)
#pragma unroll
        for (int nt = 0; nt < 4; nt++) {
            int r0 = row0 + wm * 64 + mt * 16 + gid;
            int c0 = col0 + wn * 32 + nt * 8 + tg * 2;
            float b0 = bias[c0], b1 = bias[c0 + 1];
            float v0 = acc[mt][nt][0] + b0, v1 = acc[mt][nt][1] + b1;
            float v2 = acc[mt][nt][2] + b0, v3 = acc[mt][nt][3] + b1;
            if (resid) {
                float2 ra = __half22float2(*(const __half2*)(resid + (size_t)r0 * M + c0));
                float2 rb = __half22float2(*(const __half2*)(resid + (size_t)(r0 + 8) * M + c0));
                v0 += ra.x; v1 += ra.y; v2 += rb.x; v3 += rb.y;
            }
            if (relu) {
                v0 = fmaxf(v0, 0.f); v1 = fmaxf(v1, 0.f);
                v2 = fmaxf(v2, 0.f); v3 = fmaxf(v3, 0.f);
            }
            *(__half2*)(Ch + (size_t)r0 * M + c0)       = __floats2half2_rn(v0, v1);
            *(__half2*)(Ch + (size_t)(r0 + 8) * M + c0) = __floats2half2_rn(v2, v3);
        }
}

// ---------------- fused GEMM + residual + LayerNorm (3-CTA cluster) ---------
template <int K, bool F32OUT>
__global__ void __launch_bounds__(256, 2) __cluster_dims__(3, 1, 1)
gemm_ln(const __half* __restrict__ A, const __half* __restrict__ Wt,
        const float* __restrict__ bias, const __half* __restrict__ resid,
        const float* __restrict__ lng, const float* __restrict__ lnb,
        __half* __restrict__ Oh, float* __restrict__ Of)
{
    extern __shared__ char gsm[];
    __shared__ float s_sum[128], s_sq[128], s_mean[128], s_inv[128];
    uint32_t sbase = smem_u32(gsm);
    int tid = threadIdx.x, lane = tid & 31, warp = tid >> 5;
    int wm = warp >> 2, wn = warp & 3;
    int gid = lane >> 2, tg = lane & 3;
    int j = lane >> 3, rr = lane & 7;
    int col0 = blockIdx.x * 128, row0 = blockIdx.y * 128;
    const int M = 384;

    if (tid < 128) { s_sum[tid] = 0.0f; s_sq[tid] = 0.0f; }

    float acc[4][4][4];
#pragma unroll
    for (int a = 0; a < 4; a++)
#pragma unroll
        for (int b = 0; b < 4; b++)
#pragma unroll
            for (int c = 0; c < 4; c++) acc[a][b][c] = 0.0f;

    gemm_mainloop<K>(acc, A, Wt, row0, col0, tid, wm, wn, j, rr, sbase);

#pragma unroll
    for (int mt = 0; mt < 4; mt++) {
        int r0 = row0 + wm * 64 + mt * 16 + gid;
        float ps0 = 0.f, sq0 = 0.f, ps1 = 0.f, sq1 = 0.f;
#pragma unroll
        for (int nt = 0; nt < 4; nt++) {
            int c0 = col0 + wn * 32 + nt * 8 + tg * 2;
            float b0 = bias[c0], b1 = bias[c0 + 1];
            float2 ra = __half22float2(*(const __half2*)(resid + (size_t)r0 * M + c0));
            float2 rb = __half22float2(*(const __half2*)(resid + (size_t)(r0 + 8) * M + c0));
            float v0 = acc[mt][nt][0] + b0 + ra.x;
            float v1 = acc[mt][nt][1] + b1 + ra.y;
            float v2 = acc[mt][nt][2] + b0 + rb.x;
            float v3 = acc[mt][nt][3] + b1 + rb.y;
            acc[mt][nt][0] = v0; acc[mt][nt][1] = v1;
            acc[mt][nt][2] = v2; acc[mt][nt][3] = v3;
            ps0 += v0 + v1; sq0 += v0 * v0 + v1 * v1;
            ps1 += v2 + v3; sq1 += v2 * v2 + v3 * v3;
        }
        ps0 += __shfl_xor_sync(~0u, ps0, 1); ps0 += __shfl_xor_sync(~0u, ps0, 2);
        sq0 += __shfl_xor_sync(~0u, sq0, 1); sq0 += __shfl_xor_sync(~0u, sq0, 2);
        ps1 += __shfl_xor_sync(~0u, ps1, 1); ps1 += __shfl_xor_sync(~0u, ps1, 2);
        sq1 += __shfl_xor_sync(~0u, sq1, 1); sq1 += __shfl_xor_sync(~0u, sq1, 2);
        if (tg == 0) {
            int rl = wm * 64 + mt * 16 + gid;
            atomicAdd(&s_sum[rl], ps0); atomicAdd(&s_sq[rl], sq0);
            atomicAdd(&s_sum[rl + 8], ps1); atomicAdd(&s_sq[rl + 8], sq1);
        }
    }

    cg::cluster_group cluster = cg::this_cluster();
    cluster.sync();
    if (tid < 128) {
        float ssum = 0.f, ssq = 0.f;
#pragma unroll
        for (int rk = 0; rk < 3; rk++) {
            const float* psu = cluster.map_shared_rank(s_sum, rk);
            const float* psq = cluster.map_shared_rank(s_sq, rk);
            ssum += psu[tid]; ssq += psq[tid];
        }
        float mean = ssum * (1.0f / EE);
        float var = ssq * (1.0f / EE) - mean * mean;
        s_mean[tid] = mean;
        s_inv[tid] = rsqrtf(var + 1e-5f);
    }
    cluster.sync();

#pragma unroll
    for (int mt = 0; mt < 4; mt++) {
        int rl = wm * 64 + mt * 16 + gid;
        int r0 = row0 + rl;
        float m0 = s_mean[rl],     i0 = s_inv[rl];
        float m1 = s_mean[rl + 8], i1 = s_inv[rl + 8];
#pragma unroll
        for (int nt = 0; nt < 4; nt++) {
            int c0 = col0 + wn * 32 + nt * 8 + tg * 2;
            float g0 = lng[c0], g1 = lng[c0 + 1];
            float bb0 = lnb[c0], bb1 = lnb[c0 + 1];
            float v0 = (acc[mt][nt][0] - m0) * i0 * g0 + bb0;
            float v1 = (acc[mt][nt][1] - m0) * i0 * g1 + bb1;
            float v2 = (acc[mt][nt][2] - m1) * i1 * g0 + bb0;
            float v3 = (acc[mt][nt][3] - m1) * i1 * g1 + bb1;
            if (F32OUT) {
                *(float2*)(Of + (size_t)r0 * M + c0)       = make_float2(v0, v1);
                *(float2*)(Of + (size_t)(r0 + 8) * M + c0) = make_float2(v2, v3);
            } else {
                *(__half2*)(Oh + (size_t)r0 * M + c0)       = __floats2half2_rn(v0, v1);
                *(__half2*)(Oh + (size_t)(r0 + 8) * M + c0) = __floats2half2_rn(v2, v3);
            }
        }
    }
}

// ---------------- flash attention: fp16x2 exp, 128 q-rows/CTA ---------------
#define AT_SMEM (16384 + 2 * 16384)

__global__ void __launch_bounds__(256, 2)
attn16_kernel(const __half* __restrict__ Qg, int ldq,
              const __half* __restrict__ Kg, const __half* __restrict__ Vg, int ldkv,
              __half* __restrict__ Og)
{
    extern __shared__ __align__(128) char asmem[];
    uint32_t sbase = smem_u32(asmem);
    uint32_t sQ = sbase;
    int tid = threadIdx.x, lane = tid & 31, w = tid >> 5;
    int gid = lane >> 2, tg = lane & 3;
    int j = lane >> 3, rr = lane & 7;

    int bid = blockIdx.x;
    int qt = (bid & 1) ^ 1;
    int h = (bid >> 1) % HH, b = bid / (2 * HH);
    int t0 = qt * 128;
    int hoff = h * HSS;

    const __half* qrow = Qg + (size_t)(b * TT + t0) * ldq + hoff;
#pragma unroll
    for (int i = 0; i < 4; i++) {
        int li = tid + i * 256; int r = li >> 3, sg = li & 7;
        cp16(sQ + sw_off(r, sg), qrow + (size_t)r * ldq + sg * 8);
    }
#define KVLOAD(ut, bufi)                                                           \
    {                                                                              \
        uint32_t sK_ = sbase + 16384u + (uint32_t)(bufi) * 16384u;                 \
        uint32_t sV_ = sK_ + 8192u;                                                \
        const __half* kr = Kg + (size_t)(b * TT + (ut) * 64) * ldkv + hoff;        \
        const __half* vr = Vg + (size_t)(b * TT + (ut) * 64) * ldkv + hoff;        \
        _Pragma("unroll")                                                          \
        for (int i = 0; i < 2; i++) {                                              \
            int li = tid + i * 256; int r = li >> 3, sg = li & 7;                  \
            cp16(sK_ + sw_off(r, sg), kr + (size_t)r * ldkv + sg * 8);             \
            cp16(sV_ + sw_off(r, sg), vr + (size_t)r * ldkv + sg * 8);             \
        }                                                                          \
        asm volatile("cp.async.commit_group;");                                    \
    }
    KVLOAD(0, 0);
    asm volatile("cp.async.wait_group 0;");
    __syncthreads();

    uint32_t qf[4][4];
#pragma unroll
    for (int ks = 0; ks < 4; ks++)
        ldsm4(qf[ks][0], qf[ks][1], qf[ks][2], qf[ks][3],
              sQ + sw_off(w * 16 + (j & 1) * 8 + rr, ks * 2 + (j >> 1)));

    float o[8][4];
#pragma unroll
    for (int nt = 0; nt < 8; nt++)
#pragma unroll
        for (int e = 0; e < 4; e++) o[nt][e] = 0.0f;
    float m0 = -1e30f, m1 = -1e30f, l0 = 0.0f, l1 = 0.0f;
    const float L2E = 1.44269504f;

    int nkv = 2 * (qt + 1);
    int r0g = t0 + w * 16 + gid;
    for (int ut = 0; ut < nkv; ut++) {
        if (ut > 0) { asm volatile("cp.async.wait_group 0;"); __syncthreads(); }
        if (ut < nkv - 1) KVLOAD(ut + 1, (ut + 1) & 1);
        uint32_t sK = sbase + 16384u + (uint32_t)(ut & 1) * 16384u;
        uint32_t sV = sK + 8192u;

        float s[8][4];
#pragma unroll
        for (int nt = 0; nt < 8; nt++)
#pragma unroll
            for (int e = 0; e < 4; e++) s[nt][e] = 0.0f;
#pragma unroll
        for (int ks = 0; ks < 4; ks++) {
            uint32_t kb[4][4];
#pragma unroll
            for (int p = 0; p < 4; p++)
                ldsm4(kb[p][0], kb[p][1], kb[p][2], kb[p][3],
                      sK + sw_off(p * 16 + (j >> 1) * 8 + rr, ks * 2 + (j & 1)));
#pragma unroll
            for (int nt = 0; nt < 8; nt++)
                mma16816(s[nt], qf[ks], &kb[nt >> 1][(nt & 1) * 2]);
        }
        if (ut >= 2 * qt) {
#pragma unroll
            for (int nt = 0; nt < 8; nt++) {
                int u0 = ut * 64 + nt * 8 + tg * 2;
                if (u0     > r0g)     s[nt][0] = -1e30f;
                if (u0 + 1 > r0g)     s[nt][1] = -1e30f;
                if (u0     > r0g + 8) s[nt][2] = -1e30f;
                if (u0 + 1 > r0g + 8) s[nt][3] = -1e30f;
            }
        }
        float mx0 = -1e30f, mx1 = -1e30f;
#pragma unroll
        for (int nt = 0; nt < 8; nt++) {
            mx0 = fmaxf(mx0, fmaxf(s[nt][0], s[nt][1]));
            mx1 = fmaxf(mx1, fmaxf(s[nt][2], s[nt][3]));
        }
        mx0 = fmaxf(mx0, __shfl_xor_sync(~0u, mx0, 1));
        mx0 = fmaxf(mx0, __shfl_xor_sync(~0u, mx0, 2));
        mx1 = fmaxf(mx1, __shfl_xor_sync(~0u, mx1, 1));
        mx1 = fmaxf(mx1, __shfl_xor_sync(~0u, mx1, 2));
        float mn0 = fmaxf(m0, mx0), mn1 = fmaxf(m1, mx1);
        float f0 = __expf(m0 - mn0), f1 = __expf(m1 - mn1);
        m0 = mn0; m1 = mn1;
        float a0 = mn0 * L2E, a1 = mn1 * L2E;

        // exp in fp16x2: 2 exps per MUFU op; result doubles as PV A-fragment
        uint32_t pl[8], ph_[8];
        float rs0 = 0.0f, rs1 = 0.0f;
#pragma unroll
        for (int nt = 0; nt < 8; nt++) {
            float t0v = fmaf(s[nt][0], L2E, -a0);
            float t1v = fmaf(s[nt][1], L2E, -a0);
            float t2v = fmaf(s[nt][2], L2E, -a1);
            float t3v = fmaf(s[nt][3], L2E, -a1);
            pl[nt]  = ex2_f16x2(ph2(t0v, t1v));
            ph_[nt] = ex2_f16x2(ph2(t2v, t3v));
            float2 f01 = __half22float2(*reinterpret_cast<__half2*>(&pl[nt]));
            float2 f23 = __half22float2(*reinterpret_cast<__half2*>(&ph_[nt]));
            rs0 += f01.x + f01.y;
            rs1 += f23.x + f23.y;
        }
        rs0 += __shfl_xor_sync(~0u, rs0, 1); rs0 += __shfl_xor_sync(~0u, rs0, 2);
        rs1 += __shfl_xor_sync(~0u, rs1, 1); rs1 += __shfl_xor_sync(~0u, rs1, 2);
        l0 = l0 * f0 + rs0;
        l1 = l1 * f1 + rs1;
#pragma unroll
        for (int nt = 0; nt < 8; nt++) {
            o[nt][0] *= f0; o[nt][1] *= f0; o[nt][2] *= f1; o[nt][3] *= f1;
        }
        uint32_t pa[4][4];
#pragma unroll
        for (int kk = 0; kk < 4; kk++) {
            pa[kk][0] = pl[2 * kk];
            pa[kk][1] = ph_[2 * kk];
            pa[kk][2] = pl[2 * kk + 1];
            pa[kk][3] = ph_[2 * kk + 1];
        }
#pragma unroll
        for (int kk = 0; kk < 4; kk++) {
            uint32_t vb[4][4];
#pragma unroll
            for (int p = 0; p < 4; p++)
                ldsm4t(vb[p][0], vb[p][1], vb[p][2], vb[p][3],
                       sV + sw_off(kk * 16 + (j & 1) * 8 + rr, p * 2 + (j >> 1)));
#pragma unroll
            for (int nt = 0; nt < 8; nt++)
                mma16816(o[nt], pa[kk], &vb[nt >> 1][(nt & 1) * 2]);
        }
    }
    float i0 = 1.0f / l0, i1 = 1.0f / l1;
    __half* orow = Og + (size_t)(b * TT + t0) * EE + hoff;
#pragma unroll
    for (int nt = 0; nt < 8; nt++) {
        int c = nt * 8 + tg * 2;
        *(__half2*)(orow + (size_t)(w * 16 + gid) * EE + c) =
            __floats2half2_rn(o[nt][0] * i0, o[nt][1] * i0);
        *(__half2*)(orow + (size_t)(w * 16 + gid + 8) * EE + c) =
            __floats2half2_rn(o[nt][2] * i1, o[nt][3] * i1);
    }
}

// ---------------- LayerNorm: fp16 in, one warp per row, 16 rows/CTA ---------
__global__ void __launch_bounds__(512)
ln_kernel(const __half* __restrict__ s_in,
          const float* __restrict__ g, const float* __restrict__ bt,
          __half* __restrict__ oh) {
    int warp = threadIdx.x >> 5, lane = threadIdx.x & 31;
    int row = blockIdx.x * 16 + warp;
    const uint2* rp = (const uint2*)(s_in + (size_t)row * EE);
    float v[3][4];
#pragma unroll
    for (int i = 0; i < 3; i++) {
        uint2 raw = rp[lane + 32 * i];
        float2 f0 = __half22float2(*reinterpret_cast<__half2*>(&raw.x));
        float2 f1 = __half22float2(*reinterpret_cast<__half2*>(&raw.y));
        v[i][0] = f0.x; v[i][1] = f0.y; v[i][2] = f1.x; v[i][3] = f1.y;
    }
    float s = 0.0f;
#pragma unroll
    for (int i = 0; i < 3; i++) s += v[i][0] + v[i][1] + v[i][2] + v[i][3];
#pragma unroll
    for (int off = 16; off; off >>= 1) s += __shfl_xor_sync(~0u, s, off);
    float mean = s * (1.0f / EE);
    float sq = 0.0f;
#pragma unroll
    for (int i = 0; i < 3; i++) {
        float a0 = v[i][0] - mean, a1 = v[i][1] - mean;
        float a2 = v[i][2] - mean, a3 = v[i][3] - mean;
        sq += a0 * a0 + a1 * a1 + a2 * a2 + a3 * a3;
    }
#pragma unroll
    for (int off = 16; off; off >>= 1) sq += __shfl_xor_sync(~0u, sq, off);
    float inv = rsqrtf(sq * (1.0f / EE) + 1e-5f);
    uint2* ohp = (uint2*)(oh + (size_t)row * EE);
#pragma unroll
    for (int i = 0; i < 3; i++) {
        int e4 = lane + 32 * i;
        float4 gg = *(const float4*)(g + e4 * 4);
        float4 bb = *(const float4*)(bt + e4 * 4);
        float r0 = (v[i][0] - mean) * inv * gg.x + bb.x;
        float r1 = (v[i][1] - mean) * inv * gg.y + bb.y;
        float r2 = (v[i][2] - mean) * inv * gg.z + bb.z;
        float r3 = (v[i][3] - mean) * inv * gg.w + bb.w;
        uint2 pk;
        pk.x = ph2(r0, r1);
        pk.y = ph2(r2, r3);
        ohp[e4] = pk;
    }
}

// ---------------- host orchestration ---------------------------------------
extern "C" void kernel_launch(void* const* d_in, const int* in_sizes, int n_in,
                              void* d_out, int out_size) {
    const float* enc = (const float*)d_in[0];
    const float* x   = (const float*)d_in[1];
    const float* sa1_wq = (const float*)d_in[2];
    const float* sa1_bq = (const float*)d_in[3];
    const float* sa1_wk = (const float*)d_in[4];
    const float* sa1_bk = (const float*)d_in[5];
    const float* sa1_wv = (const float*)d_in[6];
    const float* sa1_bv = (const float*)d_in[7];
    const float* sa1_pw = (const float*)d_in[8];
    const float* sa1_pb = (const float*)d_in[9];
    const float* sa2_wq = (const float*)d_in[10];
    const float* sa2_bq = (const float*)d_in[11];
    const float* sa2_wk = (const float*)d_in[12];
    const float* sa2_bk = (const float*)d_in[13];
    const float* sa2_wv = (const float*)d_in[14];
    const float* sa2_bv = (const float*)d_in[15];
    const float* sa2_pw = (const float*)d_in[16];
    const float* sa2_pb = (const float*)d_in[17];
    const float* ff_w1  = (const float*)d_in[18];
    const float* ff_b1  = (const float*)d_in[19];
    const float* ff_w2  = (const float*)d_in[20];
    const float* ff_b2  = (const float*)d_in[21];
    const float* ln1_g  = (const float*)d_in[22];
    const float* ln1_b  = (const float*)d_in[23];
    const float* ln2_g  = (const float*)d_in[24];
    const float* ln2_b  = (const float*)d_in[25];
    const float* ln3_g  = (const float*)d_in[26];
    const float* ln3_b  = (const float*)d_in[27];
    float* out = (float*)d_out;

    static cudaStream_t s_aux = nullptr;
    static cudaEvent_t evFork = nullptr, evActs = nullptr, evW = nullptr, evKV = nullptr;
    if (!s_aux) {
        cudaStreamCreateWithFlags(&s_aux, cudaStreamNonBlocking);
        cudaEventCreateWithFlags(&evFork, cudaEventDisableTiming);
        cudaEventCreateWithFlags(&evActs, cudaEventDisableTiming);
        cudaEventCreateWithFlags(&evW,    cudaEventDisableTiming);
        cudaEventCreateWithFlags(&evKV,   cudaEventDisableTiming);
        cudaFuncSetAttribute(gemm_std<384>,
                             cudaFuncAttributeMaxDynamicSharedMemorySize, G16_SMEM);
        cudaFuncSetAttribute(gemm_std<1536>,
                             cudaFuncAttributeMaxDynamicSharedMemorySize, G16_SMEM);
        cudaFuncSetAttribute(gemm_ln<1536, true>,
                             cudaFuncAttributeMaxDynamicSharedMemorySize, G16_SMEM);
        cudaFuncSetAttribute(attn16_kernel,
                             cudaFuncAttributeMaxDynamicSharedMemorySize, AT_SMEM);
    }

    __half *pqkv, *pkv, *pq, *patt, *phid, *pxh, *pench, *po1h, *po2h, *pbufh;
    __half *pwqkv, *pwq2, *pwkv, *pwp1, *pwp2, *pwf1, *pwf2;
    float *pbqkv, *pbkv, *pbq2;
    cudaGetSymbolAddress((void**)&pqkv,  g_qkv_h);
    cudaGetSymbolAddress((void**)&pkv,   g_kv_h);
    cudaGetSymbolAddress((void**)&pq,    g_q_h);
    cudaGetSymbolAddress((void**)&patt,  g_att_h);
    cudaGetSymbolAddress((void**)&phid,  g_hid_h);
    cudaGetSymbolAddress((void**)&pxh,   g_xh);
    cudaGetSymbolAddress((void**)&pench, g_ench);
    cudaGetSymbolAddress((void**)&po1h,  g_po1h);
    cudaGetSymbolAddress((void**)&po2h,  g_po2h);
    cudaGetSymbolAddress((void**)&pbufh, g_bufh);
    cudaGetSymbolAddress((void**)&pwqkv, g_wqkvh);
    cudaGetSymbolAddress((void**)&pwq2,  g_wq2h);
    cudaGetSymbolAddress((void**)&pwkv,  g_wkvh);
    cudaGetSymbolAddress((void**)&pwp1,  g_wp1h);
    cudaGetSymbolAddress((void**)&pwp2,  g_wp2h);
    cudaGetSymbolAddress((void**)&pwf1,  g_wf1h);
    cudaGetSymbolAddress((void**)&pwf2,  g_wf2h);
    cudaGetSymbolAddress((void**)&pbqkv, g_bqkv);
    cudaGetSymbolAddress((void**)&pbkv,  g_bkv);
    cudaGetSymbolAddress((void**)&pbq2,  g_bq2);

    cudaEventRecord(evFork, 0);
    cudaStreamWaitEvent(s_aux, evFork, 0);

    packB_kernel<<<PB_TOTAL, 256, 0, s_aux>>>(
        sa2_wq, sa1_pw, sa2_pw, ff_w1, ff_w2,
        pwq2, pwp1, pwp2, pwf1, pwf2);
    cudaEventRecord(evW, s_aux);

    packA_kernel<<<PA_TOTAL, 256>>>(
        sa1_wq, sa1_wk, sa1_wv, sa2_wk, sa2_wv,
        sa1_bq, sa1_bk, sa1_bv, sa2_bq, sa2_bk, sa2_bv,
        x, enc,
        pwqkv, pwkv, pbqkv, pbkv, pbq2, pxh, pench);
    cudaEventRecord(evActs, 0);

    cudaStreamWaitEvent(s_aux, evActs, 0);
    gemm_std<384><<<dim3(6, 128), 256, G16_SMEM, s_aux>>>(
        pench, pwkv, pbkv, nullptr, pkv, 2 * EE, 0);
    cudaEventRecord(evKV, s_aux);

    gemm_std<384><<<dim3(9, 128), 256, G16_SMEM>>>(
        pxh, pwqkv, pbqkv, nullptr, pqkv, 3 * EE, 0);
    attn16_kernel<<<BB * HH * 2, 256, AT_SMEM>>>(pqkv, 3 * EE,
                                                 pqkv + EE, pqkv + 2 * EE, 3 * EE, patt);

    cudaStreamWaitEvent(0, evW, 0);
    gemm_std<384><<<dim3(3, 128), 256, G16_SMEM>>>(
        patt, pwp1, sa1_pb, pxh, pbufh, EE, 0);                 // bufh = x + proj
    ln_kernel<<<NROWS / 16, 512>>>(pbufh, ln1_g, ln1_b, po1h);

    gemm_std<384><<<dim3(3, 128), 256, G16_SMEM>>>(
        po1h, pwq2, pbq2, nullptr, pq, EE, 0);
    cudaStreamWaitEvent(0, evKV, 0);
    attn16_kernel<<<BB * HH * 2, 256, AT_SMEM>>>(pq, EE,
                                                 pkv, pkv + EE, 2 * EE, patt);
    gemm_std<384><<<dim3(3, 128), 256, G16_SMEM>>>(
        patt, pwp2, sa2_pb, po1h, pbufh, EE, 0);                // bufh = o1 + proj
    ln_kernel<<<NROWS / 16, 512>>>(pbufh, ln2_g, ln2_b, po2h);

    gemm_std<384><<<dim3(12, 128), 256, G16_SMEM>>>(
        po2h, pwf1, ff_b1, nullptr, phid, FFD, 1);
    gemm_ln<1536, true><<<dim3(3, 128), 256, G16_SMEM>>>(
        phid, pwf2, ff_b2, po2h, ln3_g, ln3_b, nullptr, out);
}

// round 17
// speedup vs baseline: 1.0359x; 1.0129x over previous
#include <cuda_runtime.h>
#include <cuda_fp16.h>
#include <cooperative_groups.h>
#include <cstdint>
#include <cstddef>

namespace cg = cooperative_groups;

// Problem constants
#define EE   384
#define HH   6
#define HSS  64
#define BB   64
#define TT   256
#define FFD  1536
#define NROWS (BB*TT)          // 16384

// ---------------- scratch (device globals; no allocation allowed) ----------
__device__ __half g_qkv_h[(size_t)NROWS * 3 * EE];
__device__ __half g_kv_h[(size_t)NROWS * 2 * EE];
__device__ __half g_q_h[(size_t)NROWS * EE];
__device__ __half g_att_h[(size_t)NROWS * EE];
__device__ __half g_hid_h[(size_t)NROWS * FFD];
__device__ __half g_xh[(size_t)NROWS * EE];
__device__ __half g_ench[(size_t)NROWS * EE];
__device__ __half g_po1h[(size_t)NROWS * EE];
__device__ __half g_po2h[(size_t)NROWS * EE];
__device__ __half g_bufh[(size_t)NROWS * EE];
// fp16 weights, transposed to [out][in]
__device__ __half g_wqkvh[3 * EE * EE];
__device__ __half g_wq2h[EE * EE];
__device__ __half g_wkvh[2 * EE * EE];
__device__ __half g_wp1h[EE * EE];
__device__ __half g_wp2h[EE * EE];
__device__ __half g_wf1h[FFD * EE];
__device__ __half g_wf2h[EE * FFD];
__device__ float  g_bqkv[3 * EE];
__device__ float  g_bkv[2 * EE];
__device__ float  g_bq2[EE];

// ---------------- PTX helpers ----------------------------------------------
__device__ __forceinline__ uint32_t smem_u32(const void* p) {
    uint32_t a;
    asm("{ .reg .u64 t; cvta.to.shared.u64 t, %1; cvt.u32.u64 %0, t; }" : "=r"(a) : "l"(p));
    return a;
}
__device__ __forceinline__ void cp16(uint32_t dst, const void* src) {
    asm volatile("cp.async.cg.shared.global [%0], [%1], 16;" :: "r"(dst), "l"(src));
}
__device__ __forceinline__ void ldsm4(uint32_t& r0, uint32_t& r1, uint32_t& r2, uint32_t& r3,
                                      uint32_t addr) {
    asm volatile("ldmatrix.sync.aligned.m8n8.x4.shared.b16 {%0,%1,%2,%3}, [%4];"
                 : "=r"(r0), "=r"(r1), "=r"(r2), "=r"(r3) : "r"(addr));
}
__device__ __forceinline__ void ldsm4t(uint32_t& r0, uint32_t& r1, uint32_t& r2, uint32_t& r3,
                                       uint32_t addr) {
    asm volatile("ldmatrix.sync.aligned.m8n8.x4.trans.shared.b16 {%0,%1,%2,%3}, [%4];"
                 : "=r"(r0), "=r"(r1), "=r"(r2), "=r"(r3) : "r"(addr));
}
__device__ __forceinline__ void mma16816(float* c, const uint32_t* a, const uint32_t* b) {
    asm volatile(
        "mma.sync.aligned.m16n8k16.row.col.f32.f16.f16.f32 "
        "{%0,%1,%2,%3}, {%4,%5,%6,%7}, {%8,%9}, {%0,%1,%2,%3};"
        : "+f"(c[0]), "+f"(c[1]), "+f"(c[2]), "+f"(c[3])
        : "r"(a[0]), "r"(a[1]), "r"(a[2]), "r"(a[3]), "r"(b[0]), "r"(b[1]));
}
__device__ __forceinline__ uint32_t ph2(float a, float b) {
    __half2 h = __floats2half2_rn(a, b);
    return *reinterpret_cast<uint32_t*>(&h);
}
__device__ __forceinline__ uint32_t ex2_f16x2(uint32_t in) {
    uint32_t out;
    asm("ex2.approx.f16x2 %0, %1;" : "=r"(out) : "r"(in));
    return out;
}
__device__ __forceinline__ uint32_t sw_off(int r, int seg) {
    return (uint32_t)(r * 128 + (((seg ^ (r & 7)) & 7) << 4));
}

// ---------------- shared 32x32 transpose tile -------------------------------
__device__ __forceinline__ void transpose32(const float* __restrict__ src, int lds,
                                            __half* __restrict__ dst, int ldd,
                                            int r0, int c0, float scale, int tid) {
    __shared__ float ttile[32][33];
    int tx = tid & 31, ty = tid >> 5;
#pragma unroll
    for (int i = 0; i < 4; i++) {
        int row = ty + i * 8;
        ttile[row][tx] = src[(size_t)(r0 + row) * lds + c0 + tx] * scale;
    }
    __syncthreads();
#pragma unroll
    for (int i = 0; i < 4; i++) {
        int row = ty + i * 8;
        dst[(size_t)(c0 + row) * ldd + r0 + tx] = __float2half_rn(ttile[tx][row]);
    }
}

// ---------------- packA: critical path -------------------------------------
#define PA_T   720
#define PA_B   (PA_T + 9)
#define NACTV  ((long long)((size_t)NROWS * EE / 4))
#define PA_TOTAL (PA_B + 12288)

__global__ void __launch_bounds__(256)
packA_kernel(
    const float* __restrict__ wq1, const float* __restrict__ wk1, const float* __restrict__ wv1,
    const float* __restrict__ wk2, const float* __restrict__ wv2,
    const float* __restrict__ bq1, const float* __restrict__ bk1, const float* __restrict__ bv1,
    const float* __restrict__ bq2, const float* __restrict__ bk2, const float* __restrict__ bv2,
    const float* __restrict__ x, const float* __restrict__ enc,
    __half* __restrict__ wqkv, __half* __restrict__ wkv,
    float* __restrict__ bqkv, float* __restrict__ bkv, float* __restrict__ bq2o,
    __half* __restrict__ xh, __half* __restrict__ ench)
{
    int bid = blockIdx.x, tid = threadIdx.x;
    if (bid < PA_T) {
        int tensor = bid / 144, rem = bid % 144;
        int h = rem / 24, t = rem % 24;
        int r0 = (t >> 1) * 32, c0 = (t & 1) * 32;
        const float* srcs[5] = {wq1, wk1, wv1, wk2, wv2};
        const float* src = srcs[tensor] + (size_t)h * EE * HSS;
        __half* dst; int rowoff;
        if (tensor < 3) { dst = wqkv; rowoff = tensor * EE; }
        else            { dst = wkv;  rowoff = (tensor - 3) * EE; }
        dst += (size_t)(rowoff + h * HSS) * EE;
        float scale = (tensor == 0) ? rsqrtf((float)EE) : 1.0f;
        transpose32(src, HSS, dst, EE, r0, c0, scale, tid);
        return;
    }
    if (bid < PA_B) {
        int i = (bid - PA_T) * 256 + tid;
        float scale = rsqrtf((float)EE);
        if (i < 3 * EE) {
            int sub = i / EE, jj = i % EE;
            bqkv[i] = sub == 0 ? bq1[jj] * scale : sub == 1 ? bk1[jj] : bv1[jj];
        } else if (i < 5 * EE) {
            int k = i - 3 * EE;
            bkv[k] = k < EE ? bk2[k] : bv2[k - EE];
        } else {
            int k = i - 5 * EE;
            bq2o[k] = bq2[k] * scale;
        }
        return;
    }
    long long ai = (long long)(bid - PA_B) * 256 + tid;
    const float* srcf; __half* dsth;
    if (ai < NACTV) { srcf = x; dsth = xh; }
    else { ai -= NACTV; srcf = enc; dsth = ench; }
    float4 v4 = ((const float4*)srcf)[ai];
    ((__half2*)dsth)[2 * ai]     = __floats2half2_rn(v4.x, v4.y);
    ((__half2*)dsth)[2 * ai + 1] = __floats2half2_rn(v4.z, v4.w);
}

// ---------------- packB: off-critical-path weight transposes ----------------
#define PB_WQ2 144
#define PB_PW  (PB_WQ2 + 288)
#define PB_F1  (PB_PW + 576)
#define PB_TOTAL (PB_F1 + 576)

__global__ void __launch_bounds__(256)
packB_kernel(const float* __restrict__ wq2,
             const float* __restrict__ pw1, const float* __restrict__ pw2,
             const float* __restrict__ fw1, const float* __restrict__ fw2,
             __half* __restrict__ wqo, __half* __restrict__ wp1o, __half* __restrict__ wp2o,
             __half* __restrict__ wf1o, __half* __restrict__ wf2o)
{
    int bid = blockIdx.x, tid = threadIdx.x;
    if (bid < PB_WQ2) {
        int h = bid / 24, t = bid % 24;
        int r0 = (t >> 1) * 32, c0 = (t & 1) * 32;
        transpose32(wq2 + (size_t)h * EE * HSS, HSS,
                    wqo + (size_t)(h * HSS) * EE, EE,
                    r0, c0, rsqrtf((float)EE), tid);
    } else if (bid < PB_PW) {
        int j = bid - PB_WQ2, which = j / 144, t = j % 144;
        int r0 = (t / 12) * 32, c0 = (t % 12) * 32;
        transpose32(which ? pw2 : pw1, EE, which ? wp2o : wp1o, EE, r0, c0, 1.0f, tid);
    } else if (bid < PB_F1) {
        int t = bid - PB_PW;
        int r0 = (t / 48) * 32, c0 = (t % 48) * 32;
        transpose32(fw1, FFD, wf1o, EE, r0, c0, 1.0f, tid);
    } else {
        int t = bid - PB_F1;
        int r0 = (t / 12) * 32, c0 = (t % 12) * 32;
        transpose32(fw2, EE, wf2o, FFD, r0, c0, 1.0f, tid);
    }
}

// ---------------- fp16 tensor-core GEMM mainloop (128x128, BK=64) -----------
#define G16_SMEM (3 * 32768)

template <int K>
__device__ __forceinline__ void load_chunk(uint32_t sbase,
                                           const __half* __restrict__ A,
                                           const __half* __restrict__ Wt,
                                           int row0, int col0, int tid,
                                           int stage, int kt) {
    uint32_t sA = sbase + (uint32_t)stage * 32768u;
    uint32_t sB = sA + 16384u;
#pragma unroll
    for (int i = 0; i < 4; i++) {
        int li = tid + i * 256; int r = li >> 3, sg = li & 7;
        cp16(sA + sw_off(r, sg), A + (size_t)(row0 + r) * K + kt + sg * 8);
        cp16(sB + sw_off(r, sg), Wt + (size_t)(col0 + r) * K + kt + sg * 8);
    }
    asm volatile("cp.async.commit_group;");
}

template <int K>
__device__ __forceinline__ void gemm_mainloop(float acc[4][4][4],
                                              const __half* __restrict__ A,
                                              const __half* __restrict__ Wt,
                                              int row0, int col0, int tid,
                                              int wm, int wn, int j, int rr,
                                              uint32_t sbase)
{
    constexpr int nch = K >> 6;
    load_chunk<K>(sbase, A, Wt, row0, col0, tid, 0, 0);
    load_chunk<K>(sbase, A, Wt, row0, col0, tid, 1, 64);
#pragma unroll 2
    for (int it = 0; it < nch; it++) {
        if (it + 1 < nch) asm volatile("cp.async.wait_group 1;");
        else              asm volatile("cp.async.wait_group 0;");
        __syncthreads();
        if (it + 2 < nch)
            load_chunk<K>(sbase, A, Wt, row0, col0, tid, (it + 2) % 3, (it + 2) * 64);
        uint32_t sA = sbase + (uint32_t)(it % 3) * 32768u;
        uint32_t sB = sA + 16384u;
#pragma unroll
        for (int ks = 0; ks < 4; ks++) {
            uint32_t a[4][4], bfr[2][4];
#pragma unroll
            for (int mt = 0; mt < 4; mt++)
                ldsm4(a[mt][0], a[mt][1], a[mt][2], a[mt][3],
                      sA + sw_off(wm * 64 + mt * 16 + (j & 1) * 8 + rr, ks * 2 + (j >> 1)));
#pragma unroll
            for (int p = 0; p < 2; p++)
                ldsm4(bfr[p][0], bfr[p][1], bfr[p][2], bfr[p][3],
                      sB + sw_off(wn * 32 + p * 16 + (j >> 1) * 8 + rr, ks * 2 + (j & 1)));
#pragma unroll
            for (int mt = 0; mt < 4; mt++)
#pragma unroll
                for (int nt = 0; nt < 4; nt++)
                    mma16816(acc[mt][nt], a[mt], &bfr[nt >> 1][(nt & 1) * 2]);
        }
    }
}

// ---------------- plain GEMM (bias, opt resid/relu, fp16 out) ---------------
template <int K>
__global__ void __launch_bounds__(256, 2)
gemm_std(const __half* __restrict__ A, const __half* __restrict__ Wt,
         const float* __restrict__ bias, const __half* __restrict__ resid,
         __half* __restrict__ Ch, int M, int relu)
{
    extern __shared__ char gsm[];
    uint32_t sbase = smem_u32(gsm);
    int tid = threadIdx.x, lane = tid & 31, warp = tid >> 5;
    int wm = warp >> 2, wn = warp & 3;
    int gid = lane >> 2, tg = lane & 3;
    int j = lane >> 3, rr = lane & 7;
    int col0 = blockIdx.x * 128, row0 = blockIdx.y * 128;

    float acc[4][4][4];
#pragma unroll
    for (int a = 0; a < 4; a++)
#pragma unroll
        for (int b = 0; b < 4; b++)
#pragma unroll
            for (int c = 0; c < 4; c++) acc[a][b][c] = 0.0f;

    gemm_mainloop<K>(acc, A, Wt, row0, col0, tid, wm, wn, j, rr, sbase);

#pragma unroll
    for (int mt = 0; mt < 4; mt++)
#pragma unroll
        for (int nt = 0; nt < 4; nt++) {
            int r0 = row0 + wm * 64 + mt * 16 + gid;
            int c0 = col0 + wn * 32 + nt * 8 + tg * 2;
            float b0 = bias[c0], b1 = bias[c0 + 1];
            float v0 = acc[mt][nt][0] + b0, v1 = acc[mt][nt][1] + b1;
            float v2 = acc[mt][nt][2] + b0, v3 = acc[mt][nt][3] + b1;
            if (resid) {
                float2 ra = __half22float2(*(const __half2*)(resid + (size_t)r0 * M + c0));
                float2 rb = __half22float2(*(const __half2*)(resid + (size_t)(r0 + 8) * M + c0));
                v0 += ra.x; v1 += ra.y; v2 += rb.x; v3 += rb.y;
            }
            if (relu) {
                v0 = fmaxf(v0, 0.f); v1 = fmaxf(v1, 0.f);
                v2 = fmaxf(v2, 0.f); v3 = fmaxf(v3, 0.f);
            }
            *(__half2*)(Ch + (size_t)r0 * M + c0)       = __floats2half2_rn(v0, v1);
            *(__half2*)(Ch + (size_t)(r0 + 8) * M + c0) = __floats2half2_rn(v2, v3);
        }
}

// ---------------- fused GEMM + residual + LayerNorm (3-CTA cluster) ---------
template <int K, bool F32OUT>
__global__ void __launch_bounds__(256, 2) __cluster_dims__(3, 1, 1)
gemm_ln(const __half* __restrict__ A, const __half* __restrict__ Wt,
        const float* __restrict__ bias, const __half* __restrict__ resid,
        const float* __restrict__ lng, const float* __restrict__ lnb,
        __half* __restrict__ Oh, float* __restrict__ Of)
{
    extern __shared__ char gsm[];
    __shared__ float s_sum[128], s_sq[128], s_mean[128], s_inv[128];
    uint32_t sbase = smem_u32(gsm);
    int tid = threadIdx.x, lane = tid & 31, warp = tid >> 5;
    int wm = warp >> 2, wn = warp & 3;
    int gid = lane >> 2, tg = lane & 3;
    int j = lane >> 3, rr = lane & 7;
    int col0 = blockIdx.x * 128, row0 = blockIdx.y * 128;
    const int M = 384;

    if (tid < 128) { s_sum[tid] = 0.0f; s_sq[tid] = 0.0f; }

    float acc[4][4][4];
#pragma unroll
    for (int a = 0; a < 4; a++)
#pragma unroll
        for (int b = 0; b < 4; b++)
#pragma unroll
            for (int c = 0; c < 4; c++) acc[a][b][c] = 0.0f;

    gemm_mainloop<K>(acc, A, Wt, row0, col0, tid, wm, wn, j, rr, sbase);

#pragma unroll
    for (int mt = 0; mt < 4; mt++) {
        int r0 = row0 + wm * 64 + mt * 16 + gid;
        float ps0 = 0.f, sq0 = 0.f, ps1 = 0.f, sq1 = 0.f;
#pragma unroll
        for (int nt = 0; nt < 4; nt++) {
            int c0 = col0 + wn * 32 + nt * 8 + tg * 2;
            float b0 = bias[c0], b1 = bias[c0 + 1];
            float2 ra = __half22float2(*(const __half2*)(resid + (size_t)r0 * M + c0));
            float2 rb = __half22float2(*(const __half2*)(resid + (size_t)(r0 + 8) * M + c0));
            float v0 = acc[mt][nt][0] + b0 + ra.x;
            float v1 = acc[mt][nt][1] + b1 + ra.y;
            float v2 = acc[mt][nt][2] + b0 + rb.x;
            float v3 = acc[mt][nt][3] + b1 + rb.y;
            acc[mt][nt][0] = v0; acc[mt][nt][1] = v1;
            acc[mt][nt][2] = v2; acc[mt][nt][3] = v3;
            ps0 += v0 + v1; sq0 += v0 * v0 + v1 * v1;
            ps1 += v2 + v3; sq1 += v2 * v2 + v3 * v3;
        }
        ps0 += __shfl_xor_sync(~0u, ps0, 1); ps0 += __shfl_xor_sync(~0u, ps0, 2);
        sq0 += __shfl_xor_sync(~0u, sq0, 1); sq0 += __shfl_xor_sync(~0u, sq0, 2);
        ps1 += __shfl_xor_sync(~0u, ps1, 1); ps1 += __shfl_xor_sync(~0u, ps1, 2);
        sq1 += __shfl_xor_sync(~0u, sq1, 1); sq1 += __shfl_xor_sync(~0u, sq1, 2);
        if (tg == 0) {
            int rl = wm * 64 + mt * 16 + gid;
            atomicAdd(&s_sum[rl], ps0); atomicAdd(&s_sq[rl], sq0);
            atomicAdd(&s_sum[rl + 8], ps1); atomicAdd(&s_sq[rl + 8], sq1);
        }
    }

    cg::cluster_group cluster = cg::this_cluster();
    cluster.sync();
    if (tid < 128) {
        float ssum = 0.f, ssq = 0.f;
#pragma unroll
        for (int rk = 0; rk < 3; rk++) {
            const float* psu = cluster.map_shared_rank(s_sum, rk);
            const float* psq = cluster.map_shared_rank(s_sq, rk);
            ssum += psu[tid]; ssq += psq[tid];
        }
        float mean = ssum * (1.0f / EE);
        float var = ssq * (1.0f / EE) - mean * mean;
        s_mean[tid] = mean;
        s_inv[tid] = rsqrtf(var + 1e-5f);
    }
    cluster.sync();

#pragma unroll
    for (int mt = 0; mt < 4; mt++) {
        int rl = wm * 64 + mt * 16 + gid;
        int r0 = row0 + rl;
        float m0 = s_mean[rl],     i0 = s_inv[rl];
        float m1 = s_mean[rl + 8], i1 = s_inv[rl + 8];
#pragma unroll
        for (int nt = 0; nt < 4; nt++) {
            int c0 = col0 + wn * 32 + nt * 8 + tg * 2;
            float g0 = lng[c0], g1 = lng[c0 + 1];
            float bb0 = lnb[c0], bb1 = lnb[c0 + 1];
            float v0 = (acc[mt][nt][0] - m0) * i0 * g0 + bb0;
            float v1 = (acc[mt][nt][1] - m0) * i0 * g1 + bb1;
            float v2 = (acc[mt][nt][2] - m1) * i1 * g0 + bb0;
            float v3 = (acc[mt][nt][3] - m1) * i1 * g1 + bb1;
            if (F32OUT) {
                *(float2*)(Of + (size_t)r0 * M + c0)       = make_float2(v0, v1);
                *(float2*)(Of + (size_t)(r0 + 8) * M + c0) = make_float2(v2, v3);
            } else {
                *(__half2*)(Oh + (size_t)r0 * M + c0)       = __floats2half2_rn(v0, v1);
                *(__half2*)(Oh + (size_t)(r0 + 8) * M + c0) = __floats2half2_rn(v2, v3);
            }
        }
    }
}

// ---------------- flash attention: causal warp-skip, fp16x2 exp -------------
#define AT_SMEM (16384 + 2 * 16384)

__global__ void __launch_bounds__(256, 2)
attn16_kernel(const __half* __restrict__ Qg, int ldq,
              const __half* __restrict__ Kg, const __half* __restrict__ Vg, int ldkv,
              __half* __restrict__ Og)
{
    extern __shared__ __align__(128) char asmem[];
    uint32_t sbase = smem_u32(asmem);
    uint32_t sQ = sbase;
    int tid = threadIdx.x, lane = tid & 31, w = tid >> 5;
    int gid = lane >> 2, tg = lane & 3;
    int j = lane >> 3, rr = lane & 7;

    int bid = blockIdx.x;
    int qt = (bid & 1) ^ 1;
    int h = (bid >> 1) % HH, b = bid / (2 * HH);
    int t0 = qt * 128;
    int hoff = h * HSS;

    const __half* qrow = Qg + (size_t)(b * TT + t0) * ldq + hoff;
#pragma unroll
    for (int i = 0; i < 4; i++) {
        int li = tid + i * 256; int r = li >> 3, sg = li & 7;
        cp16(sQ + sw_off(r, sg), qrow + (size_t)r * ldq + sg * 8);
    }
#define KVLOAD(ut, bufi)                                                           \
    {                                                                              \
        uint32_t sK_ = sbase + 16384u + (uint32_t)(bufi) * 16384u;                 \
        uint32_t sV_ = sK_ + 8192u;                                                \
        const __half* kr = Kg + (size_t)(b * TT + (ut) * 64) * ldkv + hoff;        \
        const __half* vr = Vg + (size_t)(b * TT + (ut) * 64) * ldkv + hoff;        \
        _Pragma("unroll")                                                          \
        for (int i = 0; i < 2; i++) {                                              \
            int li = tid + i * 256; int r = li >> 3, sg = li & 7;                  \
            cp16(sK_ + sw_off(r, sg), kr + (size_t)r * ldkv + sg * 8);             \
            cp16(sV_ + sw_off(r, sg), vr + (size_t)r * ldkv + sg * 8);             \
        }                                                                          \
        asm volatile("cp.async.commit_group;");                                    \
    }
    KVLOAD(0, 0);
    asm volatile("cp.async.wait_group 0;");
    __syncthreads();

    uint32_t qf[4][4];
#pragma unroll
    for (int ks = 0; ks < 4; ks++)
        ldsm4(qf[ks][0], qf[ks][1], qf[ks][2], qf[ks][3],
              sQ + sw_off(w * 16 + (j & 1) * 8 + rr, ks * 2 + (j >> 1)));

    float o[8][4];
#pragma unroll
    for (int nt = 0; nt < 8; nt++)
#pragma unroll
        for (int e = 0; e < 4; e++) o[nt][e] = 0.0f;
    float m0 = -1e30f, m1 = -1e30f, l0 = 0.0f, l1 = 0.0f;
    const float L2E = 1.44269504f;

    int nkv = 2 * (qt + 1);
    int r0g = t0 + w * 16 + gid;
    int wmax = t0 + w * 16 + 15;        // max q-row this warp owns
    for (int ut = 0; ut < nkv; ut++) {
        if (ut > 0) { asm volatile("cp.async.wait_group 0;"); __syncthreads(); }
        if (ut < nkv - 1) KVLOAD(ut + 1, (ut + 1) & 1);
        if (ut * 64 > wmax) continue;   // whole kv tile above causal diag for this warp
        uint32_t sK = sbase + 16384u + (uint32_t)(ut & 1) * 16384u;
        uint32_t sV = sK + 8192u;

        float s[8][4];
#pragma unroll
        for (int nt = 0; nt < 8; nt++)
#pragma unroll
            for (int e = 0; e < 4; e++) s[nt][e] = 0.0f;
#pragma unroll
        for (int ks = 0; ks < 4; ks++) {
            uint32_t kb[4][4];
#pragma unroll
            for (int p = 0; p < 4; p++)
                ldsm4(kb[p][0], kb[p][1], kb[p][2], kb[p][3],
                      sK + sw_off(p * 16 + (j >> 1) * 8 + rr, ks * 2 + (j & 1)));
#pragma unroll
            for (int nt = 0; nt < 8; nt++)
                mma16816(s[nt], qf[ks], &kb[nt >> 1][(nt & 1) * 2]);
        }
        if (ut >= 2 * qt) {
#pragma unroll
            for (int nt = 0; nt < 8; nt++) {
                int u0 = ut * 64 + nt * 8 + tg * 2;
                if (u0     > r0g)     s[nt][0] = -1e30f;
                if (u0 + 1 > r0g)     s[nt][1] = -1e30f;
                if (u0     > r0g + 8) s[nt][2] = -1e30f;
                if (u0 + 1 > r0g + 8) s[nt][3] = -1e30f;
            }
        }
        float mx0 = -1e30f, mx1 = -1e30f;
#pragma unroll
        for (int nt = 0; nt < 8; nt++) {
            mx0 = fmaxf(mx0, fmaxf(s[nt][0], s[nt][1]));
            mx1 = fmaxf(mx1, fmaxf(s[nt][2], s[nt][3]));
        }
        mx0 = fmaxf(mx0, __shfl_xor_sync(~0u, mx0, 1));
        mx0 = fmaxf(mx0, __shfl_xor_sync(~0u, mx0, 2));
        mx1 = fmaxf(mx1, __shfl_xor_sync(~0u, mx1, 1));
        mx1 = fmaxf(mx1, __shfl_xor_sync(~0u, mx1, 2));
        float mn0 = fmaxf(m0, mx0), mn1 = fmaxf(m1, mx1);
        float f0 = __expf(m0 - mn0), f1 = __expf(m1 - mn1);
        m0 = mn0; m1 = mn1;
        float a0 = mn0 * L2E, a1 = mn1 * L2E;

        uint32_t pl[8], ph_[8];
        float rs0 = 0.0f, rs1 = 0.0f;
#pragma unroll
        for (int nt = 0; nt < 8; nt++) {
            float t0v = fmaf(s[nt][0], L2E, -a0);
            float t1v = fmaf(s[nt][1], L2E, -a0);
            float t2v = fmaf(s[nt][2], L2E, -a1);
            float t3v = fmaf(s[nt][3], L2E, -a1);
            pl[nt]  = ex2_f16x2(ph2(t0v, t1v));
            ph_[nt] = ex2_f16x2(ph2(t2v, t3v));
            float2 f01 = __half22float2(*reinterpret_cast<__half2*>(&pl[nt]));
            float2 f23 = __half22float2(*reinterpret_cast<__half2*>(&ph_[nt]));
            rs0 += f01.x + f01.y;
            rs1 += f23.x + f23.y;
        }
        rs0 += __shfl_xor_sync(~0u, rs0, 1); rs0 += __shfl_xor_sync(~0u, rs0, 2);
        rs1 += __shfl_xor_sync(~0u, rs1, 1); rs1 += __shfl_xor_sync(~0u, rs1, 2);
        l0 = l0 * f0 + rs0;
        l1 = l1 * f1 + rs1;
#pragma unroll
        for (int nt = 0; nt < 8; nt++) {
            o[nt][0] *= f0; o[nt][1] *= f0; o[nt][2] *= f1; o[nt][3] *= f1;
        }
        uint32_t pa[4][4];
#pragma unroll
        for (int kk = 0; kk < 4; kk++) {
            pa[kk][0] = pl[2 * kk];
            pa[kk][1] = ph_[2 * kk];
            pa[kk][2] = pl[2 * kk + 1];
            pa[kk][3] = ph_[2 * kk + 1];
        }
#pragma unroll
        for (int kk = 0; kk < 4; kk++) {
            uint32_t vb[4][4];
#pragma unroll
            for (int p = 0; p < 4; p++)
                ldsm4t(vb[p][0], vb[p][1], vb[p][2], vb[p][3],
                       sV + sw_off(kk * 16 + (j & 1) * 8 + rr, p * 2 + (j >> 1)));
#pragma unroll
            for (int nt = 0; nt < 8; nt++)
                mma16816(o[nt], pa[kk], &vb[nt >> 1][(nt & 1) * 2]);
        }
    }
    float i0 = 1.0f / l0, i1 = 1.0f / l1;
    __half* orow = Og + (size_t)(b * TT + t0) * EE + hoff;
#pragma unroll
    for (int nt = 0; nt < 8; nt++) {
        int c = nt * 8 + tg * 2;
        *(__half2*)(orow + (size_t)(w * 16 + gid) * EE + c) =
            __floats2half2_rn(o[nt][0] * i0, o[nt][1] * i0);
        *(__half2*)(orow + (size_t)(w * 16 + gid + 8) * EE + c) =
            __floats2half2_rn(o[nt][2] * i1, o[nt][3] * i1);
    }
}

// ---------------- LayerNorm: fp16 in, one warp per row, 16 rows/CTA ---------
__global__ void __launch_bounds__(512)
ln_kernel(const __half* __restrict__ s_in,
          const float* __restrict__ g, const float* __restrict__ bt,
          __half* __restrict__ oh) {
    int warp = threadIdx.x >> 5, lane = threadIdx.x & 31;
    int row = blockIdx.x * 16 + warp;
    const uint2* rp = (const uint2*)(s_in + (size_t)row * EE);
    float v[3][4];
#pragma unroll
    for (int i = 0; i < 3; i++) {
        uint2 raw = rp[lane + 32 * i];
        float2 f0 = __half22float2(*reinterpret_cast<__half2*>(&raw.x));
        float2 f1 = __half22float2(*reinterpret_cast<__half2*>(&raw.y));
        v[i][0] = f0.x; v[i][1] = f0.y; v[i][2] = f1.x; v[i][3] = f1.y;
    }
    float s = 0.0f;
#pragma unroll
    for (int i = 0; i < 3; i++) s += v[i][0] + v[i][1] + v[i][2] + v[i][3];
#pragma unroll
    for (int off = 16; off; off >>= 1) s += __shfl_xor_sync(~0u, s, off);
    float mean = s * (1.0f / EE);
    float sq = 0.0f;
#pragma unroll
    for (int i = 0; i < 3; i++) {
        float a0 = v[i][0] - mean, a1 = v[i][1] - mean;
        float a2 = v[i][2] - mean, a3 = v[i][3] - mean;
        sq += a0 * a0 + a1 * a1 + a2 * a2 + a3 * a3;
    }
#pragma unroll
    for (int off = 16; off; off >>= 1) sq += __shfl_xor_sync(~0u, sq, off);
    float inv = rsqrtf(sq * (1.0f / EE) + 1e-5f);
    uint2* ohp = (uint2*)(oh + (size_t)row * EE);
#pragma unroll
    for (int i = 0; i < 3; i++) {
        int e4 = lane + 32 * i;
        float4 gg = *(const float4*)(g + e4 * 4);
        float4 bb = *(const float4*)(bt + e4 * 4);
        float r0 = (v[i][0] - mean) * inv * gg.x + bb.x;
        float r1 = (v[i][1] - mean) * inv * gg.y + bb.y;
        float r2 = (v[i][2] - mean) * inv * gg.z + bb.z;
        float r3 = (v[i][3] - mean) * inv * gg.w + bb.w;
        uint2 pk;
        pk.x = ph2(r0, r1);
        pk.y = ph2(r2, r3);
        ohp[e4] = pk;
    }
}

// ---------------- host orchestration ---------------------------------------
extern "C" void kernel_launch(void* const* d_in, const int* in_sizes, int n_in,
                              void* d_out, int out_size) {
    const float* enc = (const float*)d_in[0];
    const float* x   = (const float*)d_in[1];
    const float* sa1_wq = (const float*)d_in[2];
    const float* sa1_bq = (const float*)d_in[3];
    const float* sa1_wk = (const float*)d_in[4];
    const float* sa1_bk = (const float*)d_in[5];
    const float* sa1_wv = (const float*)d_in[6];
    const float* sa1_bv = (const float*)d_in[7];
    const float* sa1_pw = (const float*)d_in[8];
    const float* sa1_pb = (const float*)d_in[9];
    const float* sa2_wq = (const float*)d_in[10];
    const float* sa2_bq = (const float*)d_in[11];
    const float* sa2_wk = (const float*)d_in[12];
    const float* sa2_bk = (const float*)d_in[13];
    const float* sa2_wv = (const float*)d_in[14];
    const float* sa2_bv = (const float*)d_in[15];
    const float* sa2_pw = (const float*)d_in[16];
    const float* sa2_pb = (const float*)d_in[17];
    const float* ff_w1  = (const float*)d_in[18];
    const float* ff_b1  = (const float*)d_in[19];
    const float* ff_w2  = (const float*)d_in[20];
    const float* ff_b2  = (const float*)d_in[21];
    const float* ln1_g  = (const float*)d_in[22];
    const float* ln1_b  = (const float*)d_in[23];
    const float* ln2_g  = (const float*)d_in[24];
    const float* ln2_b  = (const float*)d_in[25];
    const float* ln3_g  = (const float*)d_in[26];
    const float* ln3_b  = (const float*)d_in[27];
    float* out = (float*)d_out;

    static cudaStream_t s_aux = nullptr;
    static cudaEvent_t evFork = nullptr, evActs = nullptr, evW = nullptr, evKV = nullptr;
    if (!s_aux) {
        cudaStreamCreateWithFlags(&s_aux, cudaStreamNonBlocking);
        cudaEventCreateWithFlags(&evFork, cudaEventDisableTiming);
        cudaEventCreateWithFlags(&evActs, cudaEventDisableTiming);
        cudaEventCreateWithFlags(&evW,    cudaEventDisableTiming);
        cudaEventCreateWithFlags(&evKV,   cudaEventDisableTiming);
        cudaFuncSetAttribute(gemm_std<384>,
                             cudaFuncAttributeMaxDynamicSharedMemorySize, G16_SMEM);
        cudaFuncSetAttribute(gemm_std<1536>,
                             cudaFuncAttributeMaxDynamicSharedMemorySize, G16_SMEM);
        cudaFuncSetAttribute(gemm_ln<1536, true>,
                             cudaFuncAttributeMaxDynamicSharedMemorySize, G16_SMEM);
        cudaFuncSetAttribute(attn16_kernel,
                             cudaFuncAttributeMaxDynamicSharedMemorySize, AT_SMEM);
    }

    __half *pqkv, *pkv, *pq, *patt, *phid, *pxh, *pench, *po1h, *po2h, *pbufh;
    __half *pwqkv, *pwq2, *pwkv, *pwp1, *pwp2, *pwf1, *pwf2;
    float *pbqkv, *pbkv, *pbq2;
    cudaGetSymbolAddress((void**)&pqkv,  g_qkv_h);
    cudaGetSymbolAddress((void**)&pkv,   g_kv_h);
    cudaGetSymbolAddress((void**)&pq,    g_q_h);
    cudaGetSymbolAddress((void**)&patt,  g_att_h);
    cudaGetSymbolAddress((void**)&phid,  g_hid_h);
    cudaGetSymbolAddress((void**)&pxh,   g_xh);
    cudaGetSymbolAddress((void**)&pench, g_ench);
    cudaGetSymbolAddress((void**)&po1h,  g_po1h);
    cudaGetSymbolAddress((void**)&po2h,  g_po2h);
    cudaGetSymbolAddress((void**)&pbufh, g_bufh);
    cudaGetSymbolAddress((void**)&pwqkv, g_wqkvh);
    cudaGetSymbolAddress((void**)&pwq2,  g_wq2h);
    cudaGetSymbolAddress((void**)&pwkv,  g_wkvh);
    cudaGetSymbolAddress((void**)&pwp1,  g_wp1h);
    cudaGetSymbolAddress((void**)&pwp2,  g_wp2h);
    cudaGetSymbolAddress((void**)&pwf1,  g_wf1h);
    cudaGetSymbolAddress((void**)&pwf2,  g_wf2h);
    cudaGetSymbolAddress((void**)&pbqkv, g_bqkv);
    cudaGetSymbolAddress((void**)&pbkv,  g_bkv);
    cudaGetSymbolAddress((void**)&pbq2,  g_bq2);

    cudaEventRecord(evFork, 0);
    cudaStreamWaitEvent(s_aux, evFork, 0);

    packB_kernel<<<PB_TOTAL, 256, 0, s_aux>>>(
        sa2_wq, sa1_pw, sa2_pw, ff_w1, ff_w2,
        pwq2, pwp1, pwp2, pwf1, pwf2);
    cudaEventRecord(evW, s_aux);

    packA_kernel<<<PA_TOTAL, 256>>>(
        sa1_wq, sa1_wk, sa1_wv, sa2_wk, sa2_wv,
        sa1_bq, sa1_bk, sa1_bv, sa2_bq, sa2_bk, sa2_bv,
        x, enc,
        pwqkv, pwkv, pbqkv, pbkv, pbq2, pxh, pench);
    cudaEventRecord(evActs, 0);

    cudaStreamWaitEvent(s_aux, evActs, 0);
    gemm_std<384><<<dim3(6, 128), 256, G16_SMEM, s_aux>>>(
        pench, pwkv, pbkv, nullptr, pkv, 2 * EE, 0);
    cudaEventRecord(evKV, s_aux);

    gemm_std<384><<<dim3(9, 128), 256, G16_SMEM>>>(
        pxh, pwqkv, pbqkv, nullptr, pqkv, 3 * EE, 0);
    attn16_kernel<<<BB * HH * 2, 256, AT_SMEM>>>(pqkv, 3 * EE,
                                                 pqkv + EE, pqkv + 2 * EE, 3 * EE, patt);

    cudaStreamWaitEvent(0, evW, 0);
    gemm_std<384><<<dim3(3, 128), 256, G16_SMEM>>>(
        patt, pwp1, sa1_pb, pxh, pbufh, EE, 0);                 // bufh = x + proj
    ln_kernel<<<NROWS / 16, 512>>>(pbufh, ln1_g, ln1_b, po1h);

    gemm_std<384><<<dim3(3, 128), 256, G16_SMEM>>>(
        po1h, pwq2, pbq2, nullptr, pq, EE, 0);
    cudaStreamWaitEvent(0, evKV, 0);
    attn16_kernel<<<BB * HH * 2, 256, AT_SMEM>>>(pq, EE,
                                                 pkv, pkv + EE, 2 * EE, patt);
    gemm_std<384><<<dim3(3, 128), 256, G16_SMEM>>>(
        patt, pwp2, sa2_pb, po1h, pbufh, EE, 0);                // bufh = o1 + proj
    ln_kernel<<<NROWS / 16, 512>>>(pbufh, ln2_g, ln2_b, po2h);

    gemm_std<384><<<dim3(12, 128), 256, G16_SMEM>>>(
        po2h, pwf1, ff_b1, nullptr, phid, FFD, 1);
    gemm_ln<1536, true><<<dim3(3, 128), 256, G16_SMEM>>>(
        phid, pwf2, ff_b2, po2h, ln3_g, ln3_b, nullptr, out);
}